// round 5
// baseline (speedup 1.0000x reference)
#include <cuda_runtime.h>
#include <cstdint>

#define Bc   4
#define Nn   1024
#define Ee   1024
#define BHn  64
#define Mtot 4096   // B*N

// Packed (hi,lo) bf16x2 pairs: element [row][pair] covers cols 2p, 2p+1.
__device__ uint2 g_qp[Mtot * 512];
__device__ uint2 g_kp[Mtot * 512];
__device__ float g_v [Mtot * Ee];
// Packed GEMM inputs
__device__ uint2 g_xq[Mtot * 512];
__device__ uint2 g_xk[Mtot * 512];
__device__ uint2 g_xv[Mtot * 512];
__device__ uint2 g_wq[1024 * 512];
__device__ uint2 g_wk[1024 * 512];
__device__ uint2 g_wv[1024 * 512];
// Fallback weights buffer if the harness output only holds attn.
__device__ float g_w[(size_t)BHn * Nn * Nn];

// ===========================================================================
// bf16-split helpers + mma.sync (family-compatible)
// ===========================================================================
static __device__ __forceinline__ uint32_t pack_bf16(float x0, float x1) {
    uint32_t r;
    asm("cvt.rn.bf16x2.f32 %0, %1, %2;" : "=r"(r) : "f"(x1), "f"(x0));
    return r;
}
static __device__ __forceinline__ void split2(float x0, float x1, uint32_t& h, uint32_t& l) {
    h = pack_bf16(x0, x1);
    float h0 = __uint_as_float(h << 16);
    float h1 = __uint_as_float(h & 0xFFFF0000u);
    l = pack_bf16(x0 - h0, x1 - h1);
}
static __device__ __forceinline__ void mma_bf16(float* c, const uint32_t* a, const uint32_t* b) {
    asm volatile(
        "mma.sync.aligned.m16n8k16.row.col.f32.bf16.bf16.f32 "
        "{%0,%1,%2,%3}, {%4,%5,%6,%7}, {%8,%9}, {%0,%1,%2,%3};"
        : "+f"(c[0]), "+f"(c[1]), "+f"(c[2]), "+f"(c[3])
        : "r"(a[0]), "r"(a[1]), "r"(a[2]), "r"(a[3]), "r"(b[0]), "r"(b[1]));
}

// ===========================================================================
// Pack kernel: fp32 -> (hi,lo) bf16x2 packed pairs for X (q,k,v) and W (q,k,v).
// ===========================================================================
__global__ __launch_bounds__(256) void pack_kernel(
    const float* __restrict__ xq, const float* __restrict__ xk, const float* __restrict__ xv,
    const float* __restrict__ wq, const float* __restrict__ wk, const float* __restrict__ wv)
{
    const int z = blockIdx.y;
    const float* src; uint2* dst; int nf4;
    switch (z) {
        case 0: src = xq; dst = g_xq; nf4 = Mtot * 256; break;
        case 1: src = xk; dst = g_xk; nf4 = Mtot * 256; break;
        case 2: src = xv; dst = g_xv; nf4 = Mtot * 256; break;
        case 3: src = wq; dst = g_wq; nf4 = 1024 * 256; break;
        case 4: src = wk; dst = g_wk; nf4 = 1024 * 256; break;
        default: src = wv; dst = g_wv; nf4 = 1024 * 256; break;
    }
    int i = blockIdx.x * 256 + threadIdx.x;
    if (i >= nf4) return;
    float4 v = *(const float4*)(src + (size_t)i * 4);
    uint32_t h0, l0, h1, l1;
    split2(v.x, v.y, h0, l0);
    split2(v.z, v.w, h1, l1);
    dst[2 * i]     = make_uint2(h0, l0);
    dst[2 * i + 1] = make_uint2(h1, l1);
}

// ===========================================================================
// Projection GEMM: C = X @ W^T + b, packed inputs, packed Q/K outputs.
// Tile 128x128, K-chunk 32 (16 pairs), 256 threads.
// ===========================================================================
#define PSP 36
#define PROJ_SMEM_BYTES ((4 * 128 * PSP) * 4 + 512)

__global__ __launch_bounds__(256, 1) void proj_mma_kernel(
    const float* __restrict__ bq, const float* __restrict__ bk, const float* __restrict__ bv)
{
    extern __shared__ uint32_t psm[];
    uint32_t* XH = psm;
    uint32_t* XL = psm + 128 * PSP;
    uint32_t* WH = psm + 2 * 128 * PSP;
    uint32_t* WL = psm + 3 * 128 * PSP;
    float* bsm = (float*)(psm + 4 * 128 * PSP);

    const uint2* X; const uint2* W; const float* bias;
    if (blockIdx.z == 0)      { X = g_xq; W = g_wq; bias = bq; }
    else if (blockIdx.z == 1) { X = g_xk; W = g_wk; bias = bk; }
    else                      { X = g_xv; W = g_wv; bias = bv; }

    const int tid = threadIdx.x;
    const int w = tid >> 5, lane = tid & 31;
    const int g = lane >> 2, t = lane & 3;
    const int bm = blockIdx.x * 128, bn = blockIdx.y * 128;
    const int wm = w >> 2, wn = w & 3;

    if (tid < 128) bsm[tid] = bias[bn + tid];

    const uint2* Xb = X + (size_t)bm * 512;
    const uint2* Wb = W + (size_t)bn * 512;

    uint2 xr[8], wr2[8];
    #pragma unroll
    for (int s = 0; s < 8; s++) {
        int idx = tid + 256 * s, row = idx >> 4, p = idx & 15;
        xr[s]  = Xb[(size_t)row * 512 + p];
        wr2[s] = Wb[(size_t)row * 512 + p];
    }

    float acc[4][4][4];
    #pragma unroll
    for (int i = 0; i < 4; i++)
        #pragma unroll
        for (int j = 0; j < 4; j++)
            #pragma unroll
            for (int k = 0; k < 4; k++) acc[i][j][k] = 0.0f;

    for (int kc = 0; kc < 32; kc++) {
        __syncthreads();
        #pragma unroll
        for (int s = 0; s < 8; s++) {
            int idx = tid + 256 * s, row = idx >> 4, p = idx & 15;
            XH[row * PSP + p] = xr[s].x;  XL[row * PSP + p] = xr[s].y;
            WH[row * PSP + p] = wr2[s].x; WL[row * PSP + p] = wr2[s].y;
        }
        __syncthreads();
        if (kc < 31) {
            #pragma unroll
            for (int s = 0; s < 8; s++) {
                int idx = tid + 256 * s, row = idx >> 4, p = idx & 15;
                xr[s]  = Xb[(size_t)row * 512 + (kc + 1) * 16 + p];
                wr2[s] = Wb[(size_t)row * 512 + (kc + 1) * 16 + p];
            }
        }
        #pragma unroll
        for (int ks = 0; ks < 2; ks++) {
            uint32_t bhf[4][2], blf[4][2];
            #pragma unroll
            for (int nt = 0; nt < 4; nt++) {
                int rb = (wn * 32 + nt * 8 + g) * PSP + ks * 8 + t;
                bhf[nt][0] = WH[rb]; bhf[nt][1] = WH[rb + 4];
                blf[nt][0] = WL[rb]; blf[nt][1] = WL[rb + 4];
            }
            #pragma unroll
            for (int mt = 0; mt < 4; mt++) {
                int ra = (wm * 64 + mt * 16 + g) * PSP + ks * 8 + t;
                uint32_t ah[4] = {XH[ra], XH[ra + 8 * PSP], XH[ra + 4], XH[ra + 8 * PSP + 4]};
                uint32_t al[4] = {XL[ra], XL[ra + 8 * PSP], XL[ra + 4], XL[ra + 8 * PSP + 4]};
                #pragma unroll
                for (int nt = 0; nt < 4; nt++) {
                    mma_bf16(acc[mt][nt], ah, bhf[nt]);
                    mma_bf16(acc[mt][nt], ah, blf[nt]);
                    mma_bf16(acc[mt][nt], al, bhf[nt]);
                }
            }
        }
    }

    // Epilogue: z<2 -> packed uint2 (hi,lo) to g_qp/g_kp; z==2 -> fp32 to g_v.
    #pragma unroll
    for (int mt = 0; mt < 4; mt++) {
        int row = wm * 64 + mt * 16 + g;
        #pragma unroll
        for (int nt = 0; nt < 4; nt++) {
            int col = wn * 32 + nt * 8 + 2 * t;
            float bx = bsm[col], by = bsm[col + 1];
            float c00 = acc[mt][nt][0] + bx, c01 = acc[mt][nt][1] + by;
            float c10 = acc[mt][nt][2] + bx, c11 = acc[mt][nt][3] + by;
            if (blockIdx.z < 2) {
                uint2* dst = (blockIdx.z == 0) ? g_qp : g_kp;
                uint32_t h, l;
                split2(c00, c01, h, l);
                dst[(size_t)(bm + row) * 512 + ((bn + col) >> 1)] = make_uint2(h, l);
                split2(c10, c11, h, l);
                dst[(size_t)(bm + row + 8) * 512 + ((bn + col) >> 1)] = make_uint2(h, l);
            } else {
                *(float2*)(g_v + (size_t)(bm + row) * 1024 + bn + col) = make_float2(c00, c01);
                *(float2*)(g_v + (size_t)(bm + row + 8) * 1024 + bn + col) = make_float2(c10, c11);
            }
        }
    }
}

// ===========================================================================
// Attention: one CTA per (bh, 32-row tile), 512 threads (16 warps).
// View-row stride: 4096 floats = 2048 pairs.
// ===========================================================================
#define SSTR 1036
#define QH_OFF (32 * SSTR)               // 33152
#define QL_OFF (QH_OFF + 32 * 36)        // 34304
#define KH_OFF (QL_OFF + 32 * 36)        // 35456
#define KL_OFF (KH_OFF + 256 * 36)       // 44672
#define ATTN_SMEM_WORDS (KL_OFF + 256 * 36)   // 53888
#define ATTN_SMEM_BYTES (ATTN_SMEM_WORDS * 4) // 215552

__global__ __launch_bounds__(512, 1) void attn_mma_kernel(
    const float* __restrict__ bias, float* __restrict__ out_attn, float* __restrict__ w_out)
{
    extern __shared__ float sm[];
    float* S = sm;
    uint32_t* QH = (uint32_t*)(sm + QH_OFF);
    uint32_t* QL = (uint32_t*)(sm + QL_OFF);
    uint32_t* KH = (uint32_t*)(sm + KH_OFF);   // scores: K [256][36]; AV: VH [64][68]
    uint32_t* KL = (uint32_t*)(sm + KL_OFF);

    const int tid = threadIdx.x;
    const int w = tid >> 5, lane = tid & 31;
    const int g = lane >> 2, t = lane & 3;
    const int bh = blockIdx.y;
    const int r0 = blockIdx.x * 32;

    const uint2* qb = g_qp + bh * 32;   // pair base of this head slice; row stride 2048 pairs
    const uint2* kb = g_kp + bh * 32;
    const float* vb = g_v + bh * 64;
    const float* bsrc = bias + (size_t)(bh & 3) * Nn * Nn;
    float* wbase = (w_out != nullptr) ? w_out : g_w;
    float* wrow_base = wbase + (size_t)bh * Nn * Nn;

    // ---- Q fill (packed) ----
    #pragma unroll
    for (int s = 0; s < 2; s++) {
        int idx = tid + 512 * s, row = idx >> 5, p = idx & 31;
        uint2 v = qb[(size_t)(r0 + row) * 2048 + p];
        QH[row * 36 + p] = v.x;
        QL[row * 36 + p] = v.y;
    }

    // ---- prefetch K tile 0 (256 rows x 32 pairs) ----
    uint2 kr[16];
    #pragma unroll
    for (int s = 0; s < 16; s++) {
        int idx = tid + 512 * s, row = idx >> 5, p = idx & 31;
        kr[s] = kb[(size_t)row * 2048 + p];
    }

    const int wm = w >> 3, wn = w & 7;
    const int m0 = wm * 16, n0 = wn * 32;

    // ---- scores: 4 iterations of 256 columns ----
    for (int it = 0; it < 4; it++) {
        __syncthreads();
        #pragma unroll
        for (int s = 0; s < 16; s++) {
            int idx = tid + 512 * s, row = idx >> 5, p = idx & 31;
            KH[row * 36 + p] = kr[s].x;
            KL[row * 36 + p] = kr[s].y;
        }
        __syncthreads();
        if (it < 3) {
            #pragma unroll
            for (int s = 0; s < 16; s++) {
                int idx = tid + 512 * s, row = idx >> 5, p = idx & 31;
                kr[s] = kb[(size_t)((it + 1) * 256 + row) * 2048 + p];
            }
        }
        float sacc[4][4];
        #pragma unroll
        for (int i = 0; i < 4; i++)
            #pragma unroll
            for (int j = 0; j < 4; j++) sacc[i][j] = 0.0f;

        #pragma unroll
        for (int ks = 0; ks < 4; ks++) {
            uint32_t bhf[4][2], blf[4][2];
            #pragma unroll
            for (int nt = 0; nt < 4; nt++) {
                int rb = (n0 + nt * 8 + g) * 36 + ks * 8 + t;
                bhf[nt][0] = KH[rb]; bhf[nt][1] = KH[rb + 4];
                blf[nt][0] = KL[rb]; blf[nt][1] = KL[rb + 4];
            }
            int ra = (m0 + g) * 36 + ks * 8 + t;
            uint32_t ah[4] = {QH[ra], QH[ra + 8 * 36], QH[ra + 4], QH[ra + 8 * 36 + 4]};
            uint32_t al[4] = {QL[ra], QL[ra + 8 * 36], QL[ra + 4], QL[ra + 8 * 36 + 4]};
            #pragma unroll
            for (int nt = 0; nt < 4; nt++) {
                mma_bf16(sacc[nt], ah, bhf[nt]);
                mma_bf16(sacc[nt], ah, blf[nt]);
                mma_bf16(sacc[nt], al, bhf[nt]);
            }
        }

        int rowl = m0 + g;
        #pragma unroll
        for (int nt = 0; nt < 4; nt++) {
            int coll = it * 256 + n0 + nt * 8 + 2 * t;
            float2 b0 = *(const float2*)(bsrc + (size_t)(r0 + rowl) * 1024 + coll);
            float2 b1 = *(const float2*)(bsrc + (size_t)(r0 + rowl + 8) * 1024 + coll);
            *(float2*)&S[rowl * SSTR + coll] =
                make_float2(sacc[nt][0] + b0.x, sacc[nt][1] + b0.y);
            *(float2*)&S[(rowl + 8) * SSTR + coll] =
                make_float2(sacc[nt][2] + b1.x, sacc[nt][3] + b1.y);
        }
    }
    __syncthreads();

    // ---- prefetch V tile 0 ----
    float4 vr[4];
    #pragma unroll
    for (int s = 0; s < 2; s++) {
        int idx = tid + 512 * s, cp = idx & 63, dq = idx >> 6;
        vr[2 * s]     = *(const float4*)(vb + (size_t)(2 * cp) * 4096 + dq * 4);
        vr[2 * s + 1] = *(const float4*)(vb + (size_t)(2 * cp + 1) * 4096 + dq * 4);
    }

    // ---- softmax (register-resident) + packed P write + weights out ----
    #pragma unroll
    for (int rr = 0; rr < 2; rr++) {
        int i = w * 2 + rr;
        float* row = &S[i * SSTR];
        float2 ev[16];
        float m = -3.0e38f;
        #pragma unroll
        for (int j = 0; j < 16; j++) {
            ev[j] = ((float2*)row)[lane + 32 * j];
            m = fmaxf(m, fmaxf(ev[j].x, ev[j].y));
        }
        #pragma unroll
        for (int o = 16; o > 0; o >>= 1) m = fmaxf(m, __shfl_xor_sync(0xffffffffu, m, o));
        float ssum = 0.0f;
        #pragma unroll
        for (int j = 0; j < 16; j++) {
            ev[j].x = __expf(ev[j].x - m);
            ev[j].y = __expf(ev[j].y - m);
            ssum += ev[j].x + ev[j].y;
        }
        #pragma unroll
        for (int o = 16; o > 0; o >>= 1) ssum += __shfl_xor_sync(0xffffffffu, ssum, o);
        float inv = 1.0f / ssum;
        uint32_t* PH = (uint32_t*)row;
        uint32_t* PL = PH + 512;
        float* wrow = wrow_base + (size_t)(r0 + i) * 1024;
        __syncwarp();
        #pragma unroll
        for (int j = 0; j < 16; j++) {
            int cp = lane + 32 * j;
            float w0 = ev[j].x * inv, w1 = ev[j].y * inv;
            uint32_t h, l;
            split2(w0, w1, h, l);
            PH[cp] = h;
            PL[cp] = l;
            ((float2*)wrow)[cp] = make_float2(w0, w1);
        }
    }

    // ---- AV: O = P @ V, k split 4 ways across warps ----
    const int rm = w & 1, rn = (w >> 1) & 1, kh = w >> 2;
    float oacc[4][4];
    #pragma unroll
    for (int i = 0; i < 4; i++)
        #pragma unroll
        for (int j = 0; j < 4; j++) oacc[i][j] = 0.0f;

    uint32_t* VH = KH;   // [64][68]
    uint32_t* VL = KL;

    for (int ct = 0; ct < 8; ct++) {
        __syncthreads();
        #pragma unroll
        for (int s = 0; s < 2; s++) {
            int idx = tid + 512 * s, cp = idx & 63, dq = idx >> 6;
            float4 a = vr[2 * s], b = vr[2 * s + 1];
            float av[4] = {a.x, a.y, a.z, a.w}, bv2[4] = {b.x, b.y, b.z, b.w};
            #pragma unroll
            for (int j = 0; j < 4; j++) {
                uint32_t h, l;
                split2(av[j], bv2[j], h, l);
                VH[(dq * 4 + j) * 68 + cp] = h;
                VL[(dq * 4 + j) * 68 + cp] = l;
            }
        }
        __syncthreads();
        if (ct < 7) {
            #pragma unroll
            for (int s = 0; s < 2; s++) {
                int idx = tid + 512 * s, cp = idx & 63, dq = idx >> 6;
                vr[2 * s]     = *(const float4*)(vb + (size_t)((ct + 1) * 128 + 2 * cp) * 4096 + dq * 4);
                vr[2 * s + 1] = *(const float4*)(vb + (size_t)((ct + 1) * 128 + 2 * cp + 1) * 4096 + dq * 4);
            }
        }
        #pragma unroll
        for (int kk = 0; kk < 2; kk++) {
            int ks = kh * 2 + kk;
            int arow = rm * 16 + g;
            int cp0 = ct * 64 + ks * 8 + t;
            uint32_t* P0 = (uint32_t*)&S[arow * SSTR];
            uint32_t* P1 = (uint32_t*)&S[(arow + 8) * SSTR];
            uint32_t ah[4] = {P0[cp0], P1[cp0], P0[cp0 + 4], P1[cp0 + 4]};
            uint32_t al[4] = {P0[cp0 + 512], P1[cp0 + 512], P0[cp0 + 516], P1[cp0 + 516]};
            #pragma unroll
            for (int nt = 0; nt < 4; nt++) {
                int rb = (rn * 32 + nt * 8 + g) * 68 + ks * 8 + t;
                uint32_t bh2[2] = {VH[rb], VH[rb + 4]};
                uint32_t bl2[2] = {VL[rb], VL[rb + 4]};
                mma_bf16(oacc[nt], ah, bh2);
                mma_bf16(oacc[nt], ah, bl2);
                mma_bf16(oacc[nt], al, bh2);
            }
        }
    }

    // ---- combine 4 k-partials (P no longer needed; reuse S region) ----
    __syncthreads();
    float* Opart = sm;   // 3 buffers of 32x68
    if (kh > 0) {
        float* Ob = Opart + (kh - 1) * 2176;
        #pragma unroll
        for (int nt = 0; nt < 4; nt++) {
            int row = rm * 16 + g, col = rn * 32 + nt * 8 + 2 * t;
            *(float2*)&Ob[row * 68 + col] = make_float2(oacc[nt][0], oacc[nt][1]);
            *(float2*)&Ob[(row + 8) * 68 + col] = make_float2(oacc[nt][2], oacc[nt][3]);
        }
    }
    __syncthreads();
    if (kh == 0) {
        size_t ob = (size_t)(bh >> 4) * Nn * Ee + (size_t)(bh & 15) * 64;
        #pragma unroll
        for (int nt = 0; nt < 4; nt++) {
            int row = rm * 16 + g, col = rn * 32 + nt * 8 + 2 * t;
            float2 a0 = make_float2(oacc[nt][0], oacc[nt][1]);
            float2 a1 = make_float2(oacc[nt][2], oacc[nt][3]);
            #pragma unroll
            for (int b = 0; b < 3; b++) {
                float2 p0 = *(float2*)&Opart[b * 2176 + row * 68 + col];
                float2 p1 = *(float2*)&Opart[b * 2176 + (row + 8) * 68 + col];
                a0.x += p0.x; a0.y += p0.y;
                a1.x += p1.x; a1.y += p1.y;
            }
            *(float2*)&out_attn[ob + (size_t)(r0 + row) * Ee + col] = a0;
            *(float2*)&out_attn[ob + (size_t)(r0 + row + 8) * Ee + col] = a1;
        }
    }
}

// ---------------------------------------------------------------------------
extern "C" void kernel_launch(void* const* d_in, const int* in_sizes, int n_in,
                              void* d_out, int out_size) {
    const float* query = (const float*)d_in[0];
    const float* key_  = (const float*)d_in[1];
    const float* value = (const float*)d_in[2];
    const float* ab    = (const float*)d_in[3];
    const float* Wq    = (const float*)d_in[4];
    const float* bq    = (const float*)d_in[5];
    const float* Wk    = (const float*)d_in[6];
    const float* bk    = (const float*)d_in[7];
    const float* Wv    = (const float*)d_in[8];
    const float* bv    = (const float*)d_in[9];

    float* out = (float*)d_out;
    const long long attn_elems = (long long)Bc * Nn * Ee;
    const long long w_elems    = (long long)BHn * Nn * Nn;
    float* attn_out = out;
    float* w_out = nullptr;
    if ((long long)out_size >= attn_elems + w_elems) w_out = out + attn_elems;

    {
        dim3 grid(4096, 6);
        pack_kernel<<<grid, 256>>>(query, key_, value, Wq, Wk, Wv);
    }
    {
        cudaFuncSetAttribute(proj_mma_kernel, cudaFuncAttributeMaxDynamicSharedMemorySize,
                             PROJ_SMEM_BYTES);
        dim3 grid(Mtot / 128, Ee / 128, 3);
        proj_mma_kernel<<<grid, 256, PROJ_SMEM_BYTES>>>(bq, bk, bv);
    }
    {
        cudaFuncSetAttribute(attn_mma_kernel, cudaFuncAttributeMaxDynamicSharedMemorySize,
                             ATTN_SMEM_BYTES);
        dim3 grid(Nn / 32, BHn);
        attn_mma_kernel<<<grid, 512, ATTN_SMEM_BYTES>>>(ab, attn_out, w_out);
    }
}

// round 6
// speedup vs baseline: 1.2323x; 1.2323x over previous
#include <cuda_runtime.h>
#include <cstdint>

#define Bc   4
#define Nn   1024
#define Ee   1024
#define BHn  64
#define Mtot 4096   // B*N

// Separate hi/lo bf16x2 planes; pair p covers cols 2p,2p+1 of the flat buffer.
__device__ uint32_t g_qh[Mtot * 512];
__device__ uint32_t g_ql[Mtot * 512];
__device__ uint32_t g_kh[Mtot * 512];
__device__ uint32_t g_kl[Mtot * 512];
__device__ float    g_v [Mtot * Ee];
// V^T packed planes: [bh][d][cpair]  (64 x 64 x 512)
__device__ uint32_t g_vth[64 * 64 * 512];
__device__ uint32_t g_vtl[64 * 64 * 512];
// Packed GEMM inputs (interleaved uint2(h,l) — unpacked into smem planes by proj)
__device__ uint2 g_xq[Mtot * 512];
__device__ uint2 g_xk[Mtot * 512];
__device__ uint2 g_xv[Mtot * 512];
__device__ uint2 g_wq[1024 * 512];
__device__ uint2 g_wk[1024 * 512];
__device__ uint2 g_wv[1024 * 512];
// Fallback weights buffer if the harness output only holds attn.
__device__ float g_w[(size_t)BHn * Nn * Nn];

// ===========================================================================
// helpers
// ===========================================================================
static __device__ __forceinline__ uint32_t smem_u32(const void* p) {
    uint32_t a;
    asm("{ .reg .u64 t; cvta.to.shared.u64 t, %1; cvt.u32.u64 %0, t; }" : "=r"(a) : "l"(p));
    return a;
}
static __device__ __forceinline__ uint32_t pack_bf16(float x0, float x1) {
    uint32_t r;
    asm("cvt.rn.bf16x2.f32 %0, %1, %2;" : "=r"(r) : "f"(x1), "f"(x0));
    return r;
}
static __device__ __forceinline__ void split2(float x0, float x1, uint32_t& h, uint32_t& l) {
    h = pack_bf16(x0, x1);
    float h0 = __uint_as_float(h << 16);
    float h1 = __uint_as_float(h & 0xFFFF0000u);
    l = pack_bf16(x0 - h0, x1 - h1);
}
static __device__ __forceinline__ void mma_bf16(float* c, const uint32_t* a, const uint32_t* b) {
    asm volatile(
        "mma.sync.aligned.m16n8k16.row.col.f32.bf16.bf16.f32 "
        "{%0,%1,%2,%3}, {%4,%5,%6,%7}, {%8,%9}, {%0,%1,%2,%3};"
        : "+f"(c[0]), "+f"(c[1]), "+f"(c[2]), "+f"(c[3])
        : "r"(a[0]), "r"(a[1]), "r"(a[2]), "r"(a[3]), "r"(b[0]), "r"(b[1]));
}
static __device__ __forceinline__ void cp16(uint32_t dst, const void* src) {
    asm volatile("cp.async.cg.shared.global [%0], [%1], 16;" :: "r"(dst), "l"(src));
}
static __device__ __forceinline__ void cp_commit() {
    asm volatile("cp.async.commit_group;" ::: "memory");
}
template<int N> static __device__ __forceinline__ void cp_wait() {
    asm volatile("cp.async.wait_group %0;" :: "n"(N) : "memory");
}

// ===========================================================================
// Pack kernel: fp32 -> interleaved (hi,lo) uint2 pairs for proj inputs.
// ===========================================================================
__global__ __launch_bounds__(256) void pack_kernel(
    const float* __restrict__ xq, const float* __restrict__ xk, const float* __restrict__ xv,
    const float* __restrict__ wq, const float* __restrict__ wk, const float* __restrict__ wv)
{
    const int z = blockIdx.y;
    const float* src; uint2* dst; int nf4;
    switch (z) {
        case 0: src = xq; dst = g_xq; nf4 = Mtot * 256; break;
        case 1: src = xk; dst = g_xk; nf4 = Mtot * 256; break;
        case 2: src = xv; dst = g_xv; nf4 = Mtot * 256; break;
        case 3: src = wq; dst = g_wq; nf4 = 1024 * 256; break;
        case 4: src = wk; dst = g_wk; nf4 = 1024 * 256; break;
        default: src = wv; dst = g_wv; nf4 = 1024 * 256; break;
    }
    int i = blockIdx.x * 256 + threadIdx.x;
    if (i >= nf4) return;
    float4 v = *(const float4*)(src + (size_t)i * 4);
    uint32_t h0, l0, h1, l1;
    split2(v.x, v.y, h0, l0);
    split2(v.z, v.w, h1, l1);
    dst[2 * i]     = make_uint2(h0, l0);
    dst[2 * i + 1] = make_uint2(h1, l1);
}

// ===========================================================================
// Projection GEMM: C = X @ W^T + b. Q/K -> separate hi/lo planes; V -> fp32.
// ===========================================================================
#define PSP 36
#define PROJ_SMEM_BYTES ((4 * 128 * PSP) * 4 + 512)

__global__ __launch_bounds__(256, 1) void proj_mma_kernel(
    const float* __restrict__ bq, const float* __restrict__ bk, const float* __restrict__ bv)
{
    extern __shared__ uint32_t psm[];
    uint32_t* XH = psm;
    uint32_t* XL = psm + 128 * PSP;
    uint32_t* WH = psm + 2 * 128 * PSP;
    uint32_t* WL = psm + 3 * 128 * PSP;
    float* bsm = (float*)(psm + 4 * 128 * PSP);

    const uint2* X; const uint2* W; const float* bias;
    if (blockIdx.z == 0)      { X = g_xq; W = g_wq; bias = bq; }
    else if (blockIdx.z == 1) { X = g_xk; W = g_wk; bias = bk; }
    else                      { X = g_xv; W = g_wv; bias = bv; }

    const int tid = threadIdx.x;
    const int w = tid >> 5, lane = tid & 31;
    const int g = lane >> 2, t = lane & 3;
    const int bm = blockIdx.x * 128, bn = blockIdx.y * 128;
    const int wm = w >> 2, wn = w & 3;

    if (tid < 128) bsm[tid] = bias[bn + tid];

    const uint2* Xb = X + (size_t)bm * 512;
    const uint2* Wb = W + (size_t)bn * 512;

    uint2 xr[8], wr2[8];
    #pragma unroll
    for (int s = 0; s < 8; s++) {
        int idx = tid + 256 * s, row = idx >> 4, p = idx & 15;
        xr[s]  = Xb[(size_t)row * 512 + p];
        wr2[s] = Wb[(size_t)row * 512 + p];
    }

    float acc[4][4][4];
    #pragma unroll
    for (int i = 0; i < 4; i++)
        #pragma unroll
        for (int j = 0; j < 4; j++)
            #pragma unroll
            for (int k = 0; k < 4; k++) acc[i][j][k] = 0.0f;

    for (int kc = 0; kc < 32; kc++) {
        __syncthreads();
        #pragma unroll
        for (int s = 0; s < 8; s++) {
            int idx = tid + 256 * s, row = idx >> 4, p = idx & 15;
            XH[row * PSP + p] = xr[s].x;  XL[row * PSP + p] = xr[s].y;
            WH[row * PSP + p] = wr2[s].x; WL[row * PSP + p] = wr2[s].y;
        }
        __syncthreads();
        if (kc < 31) {
            #pragma unroll
            for (int s = 0; s < 8; s++) {
                int idx = tid + 256 * s, row = idx >> 4, p = idx & 15;
                xr[s]  = Xb[(size_t)row * 512 + (kc + 1) * 16 + p];
                wr2[s] = Wb[(size_t)row * 512 + (kc + 1) * 16 + p];
            }
        }
        #pragma unroll
        for (int ks = 0; ks < 2; ks++) {
            uint32_t bhf[4][2], blf[4][2];
            #pragma unroll
            for (int nt = 0; nt < 4; nt++) {
                int rb = (wn * 32 + nt * 8 + g) * PSP + ks * 8 + t;
                bhf[nt][0] = WH[rb]; bhf[nt][1] = WH[rb + 4];
                blf[nt][0] = WL[rb]; blf[nt][1] = WL[rb + 4];
            }
            #pragma unroll
            for (int mt = 0; mt < 4; mt++) {
                int ra = (wm * 64 + mt * 16 + g) * PSP + ks * 8 + t;
                uint32_t ah[4] = {XH[ra], XH[ra + 8 * PSP], XH[ra + 4], XH[ra + 8 * PSP + 4]};
                uint32_t al[4] = {XL[ra], XL[ra + 8 * PSP], XL[ra + 4], XL[ra + 8 * PSP + 4]};
                #pragma unroll
                for (int nt = 0; nt < 4; nt++) {
                    mma_bf16(acc[mt][nt], ah, bhf[nt]);
                    mma_bf16(acc[mt][nt], ah, blf[nt]);
                    mma_bf16(acc[mt][nt], al, bhf[nt]);
                }
            }
        }
    }

    #pragma unroll
    for (int mt = 0; mt < 4; mt++) {
        int row = wm * 64 + mt * 16 + g;
        #pragma unroll
        for (int nt = 0; nt < 4; nt++) {
            int col = wn * 32 + nt * 8 + 2 * t;
            float bx = bsm[col], by = bsm[col + 1];
            float c00 = acc[mt][nt][0] + bx, c01 = acc[mt][nt][1] + by;
            float c10 = acc[mt][nt][2] + bx, c11 = acc[mt][nt][3] + by;
            if (blockIdx.z < 2) {
                uint32_t* dh = (blockIdx.z == 0) ? g_qh : g_kh;
                uint32_t* dl = (blockIdx.z == 0) ? g_ql : g_kl;
                size_t p0 = (size_t)(bm + row) * 512 + ((bn + col) >> 1);
                size_t p1 = (size_t)(bm + row + 8) * 512 + ((bn + col) >> 1);
                uint32_t h, l;
                split2(c00, c01, h, l);
                dh[p0] = h; dl[p0] = l;
                split2(c10, c11, h, l);
                dh[p1] = h; dl[p1] = l;
            } else {
                *(float2*)(g_v + (size_t)(bm + row) * 1024 + bn + col) = make_float2(c00, c01);
                *(float2*)(g_v + (size_t)(bm + row + 8) * 1024 + bn + col) = make_float2(c10, c11);
            }
        }
    }
}

// ===========================================================================
// V transpose+pack: g_v (natural) -> g_vth/g_vtl [bh][d][cpair].
// One CTA per (ct, bh): 128 c x 64 d.
// ===========================================================================
__global__ __launch_bounds__(256) void vt_kernel()
{
    __shared__ uint32_t sh[64 * 65], sl[64 * 65];
    const int bh = blockIdx.y, ct = blockIdx.x, tid = threadIdx.x;

    #pragma unroll
    for (int s = 0; s < 16; s++) {
        int idx = tid + 256 * s;          // 0..4095
        int d = idx & 63, cp = idx >> 6;  // cp 0..63
        const float* p = g_v + (size_t)(ct * 128 + 2 * cp) * 4096 + bh * 64 + d;
        float x0 = p[0], x1 = p[4096];
        uint32_t h, l;
        split2(x0, x1, h, l);
        sh[cp * 65 + d] = h;
        sl[cp * 65 + d] = l;
    }
    __syncthreads();
    #pragma unroll
    for (int s = 0; s < 16; s++) {
        int idx = tid + 256 * s;
        int cp = idx & 63, d = idx >> 6;
        size_t o = ((size_t)(bh * 64 + d) << 9) + ct * 64 + cp;
        g_vth[o] = sh[cp * 65 + d];
        g_vtl[o] = sl[cp * 65 + d];
    }
}

// ===========================================================================
// Attention: one CTA per (bh, 32-row tile), 512 threads, cp.async pipelines.
// ===========================================================================
#define SSTR 1036
#define QH_OFF 33152                 // words
#define QL_OFF (QH_OFF + 1152)
#define KB_OFF (QL_OFF + 1152)       // 35456; 2 K buffers of 9216 words
#define ATTN_SMEM_WORDS (KB_OFF + 2 * 9216)   // 53888
#define ATTN_SMEM_BYTES (ATTN_SMEM_WORDS * 4) // 215552

__global__ __launch_bounds__(512, 1) void attn_mma_kernel(
    const float* __restrict__ bias, float* __restrict__ out_attn, float* __restrict__ w_out)
{
    extern __shared__ float sm[];
    float* S = sm;
    uint32_t* QH = (uint32_t*)(sm + QH_OFF);
    uint32_t* QL = (uint32_t*)(sm + QL_OFF);
    const uint32_t smb = smem_u32(sm);

    const int tid = threadIdx.x;
    const int w = tid >> 5, lane = tid & 31;
    const int g = lane >> 2, t = lane & 3;
    const int bh = blockIdx.y;
    const int r0 = blockIdx.x * 32;

    const float* bsrc = bias + (size_t)(bh & 3) * Nn * Nn;
    float* wbase = (w_out != nullptr) ? w_out : g_w;
    float* wrow_base = wbase + (size_t)bh * Nn * Nn;

    auto issueK = [&](int it) {
        int b = it & 1;
        #pragma unroll
        for (int s = 0; s < 4; s++) {
            int idx = tid + 512 * s;            // 0..2047
            int plane = idx >> 10;
            int row = (idx >> 3) & 127;
            int seg = idx & 7;
            const uint32_t* src = (plane ? g_kl : g_kh) +
                (size_t)(it * 128 + row) * 2048 + bh * 32 + seg * 4;
            uint32_t dst = smb + (uint32_t)(KB_OFF + b * 9216 + plane * 4608 +
                                            row * 36 + seg * 4) * 4;
            cp16(dst, src);
        }
        cp_commit();
    };
    auto issueV = [&](int it) {
        int b = it & 1;
        #pragma unroll
        for (int s = 0; s < 4; s++) {
            int idx = tid + 512 * s;
            int plane = idx >> 10;
            int row = (idx >> 4) & 63;          // d
            int seg = idx & 15;
            const uint32_t* src = (plane ? g_vtl : g_vth) +
                (((size_t)(bh * 64 + row)) << 9) + it * 64 + seg * 4;
            uint32_t dst = smb + (uint32_t)(KB_OFF + b * 8704 + plane * 4352 +
                                            row * 68 + seg * 4) * 4;
            cp16(dst, src);
        }
        cp_commit();
    };

    // ---- prologue: Q (group 0), K0 (group 1), K1 (group 2) ----
    {
        int plane = tid >> 8, ci = tid & 255, row = ci >> 3, seg = ci & 7;
        const uint32_t* src = (plane ? g_ql : g_qh) +
            (size_t)(r0 + row) * 2048 + bh * 32 + seg * 4;
        uint32_t dst = smb + (uint32_t)(QH_OFF + plane * 1152 + row * 36 + seg * 4) * 4;
        cp16(dst, src);
        cp_commit();
    }
    issueK(0);
    issueK(1);

    // ---- Q fragments into registers ----
    const int wm = w >> 3, wn = w & 7;
    const int m0 = wm * 16, n0 = wn * 16;
    cp_wait<2>();
    __syncthreads();
    uint32_t qah[4][4], qal[4][4];
    #pragma unroll
    for (int ks = 0; ks < 4; ks++) {
        int ra = (m0 + g) * 36 + ks * 8 + t;
        qah[ks][0] = QH[ra];     qah[ks][1] = QH[ra + 288];
        qah[ks][2] = QH[ra + 4]; qah[ks][3] = QH[ra + 292];
        qal[ks][0] = QL[ra];     qal[ks][1] = QL[ra + 288];
        qal[ks][2] = QL[ra + 4]; qal[ks][3] = QL[ra + 292];
    }

    // ---- scores: 8 iterations of 128 columns, double-buffered K ----
    #pragma unroll 1
    for (int it = 0; it < 8; it++) {
        if (it == 7) cp_wait<0>(); else cp_wait<1>();
        __syncthreads();
        const uint32_t* KHb = (const uint32_t*)(sm + KB_OFF) + (it & 1) * 9216;
        const uint32_t* KLb = KHb + 4608;

        float sacc[2][4];
        #pragma unroll
        for (int i = 0; i < 2; i++)
            #pragma unroll
            for (int j = 0; j < 4; j++) sacc[i][j] = 0.0f;

        #pragma unroll
        for (int ks = 0; ks < 4; ks++) {
            #pragma unroll
            for (int nt = 0; nt < 2; nt++) {
                int rb = (n0 + nt * 8 + g) * 36 + ks * 8 + t;
                uint32_t bhf[2] = {KHb[rb], KHb[rb + 4]};
                uint32_t blf[2] = {KLb[rb], KLb[rb + 4]};
                mma_bf16(sacc[nt], qah[ks], bhf);
                mma_bf16(sacc[nt], qah[ks], blf);
                mma_bf16(sacc[nt], qal[ks], bhf);
            }
        }

        int rowl = m0 + g;
        #pragma unroll
        for (int nt = 0; nt < 2; nt++) {
            int coll = it * 128 + n0 + nt * 8 + 2 * t;
            float2 b0 = *(const float2*)(bsrc + (size_t)(r0 + rowl) * 1024 + coll);
            float2 b1 = *(const float2*)(bsrc + (size_t)(r0 + rowl + 8) * 1024 + coll);
            *(float2*)&S[rowl * SSTR + coll] =
                make_float2(sacc[nt][0] + b0.x, sacc[nt][1] + b0.y);
            *(float2*)&S[(rowl + 8) * SSTR + coll] =
                make_float2(sacc[nt][2] + b1.x, sacc[nt][3] + b1.y);
        }
        __syncthreads();
        if (it < 6) issueK(it + 2);
    }

    // ---- V pipeline prologue (overlaps softmax) ----
    issueV(0);
    issueV(1);

    // ---- softmax (register-resident) + packed P overlay + weights out ----
    #pragma unroll
    for (int rr = 0; rr < 2; rr++) {
        int i = w * 2 + rr;
        float* row = &S[i * SSTR];
        float2 ev[16];
        float m = -3.0e38f;
        #pragma unroll
        for (int j = 0; j < 16; j++) {
            ev[j] = ((float2*)row)[lane + 32 * j];
            m = fmaxf(m, fmaxf(ev[j].x, ev[j].y));
        }
        #pragma unroll
        for (int o = 16; o > 0; o >>= 1) m = fmaxf(m, __shfl_xor_sync(0xffffffffu, m, o));
        float ssum = 0.0f;
        #pragma unroll
        for (int j = 0; j < 16; j++) {
            ev[j].x = __expf(ev[j].x - m);
            ev[j].y = __expf(ev[j].y - m);
            ssum += ev[j].x + ev[j].y;
        }
        #pragma unroll
        for (int o = 16; o > 0; o >>= 1) ssum += __shfl_xor_sync(0xffffffffu, ssum, o);
        float inv = 1.0f / ssum;
        uint32_t* PH = (uint32_t*)row;
        uint32_t* PL = PH + 512;
        float* wrow = wrow_base + (size_t)(r0 + i) * 1024;
        __syncwarp();
        #pragma unroll
        for (int j = 0; j < 16; j++) {
            int cp = lane + 32 * j;
            float w0 = ev[j].x * inv, w1 = ev[j].y * inv;
            uint32_t h, l;
            split2(w0, w1, h, l);
            PH[cp] = h;
            PL[cp] = l;
            ((float2*)wrow)[cp] = make_float2(w0, w1);
        }
    }

    // ---- AV: O = P @ V^T-tiles, k split 4 ways across warps ----
    const int rm = w & 1, rn = (w >> 1) & 1, kh = w >> 2;
    float oacc[2][4];
    #pragma unroll
    for (int i = 0; i < 2; i++)
        #pragma unroll
        for (int j = 0; j < 4; j++) oacc[i][j] = 0.0f;

    // oacc covers 16x32: nt 0..3 of 8 cols -> need 4; use [4][4]
    float oacc2[4][4];
    #pragma unroll
    for (int i = 0; i < 4; i++)
        #pragma unroll
        for (int j = 0; j < 4; j++) oacc2[i][j] = 0.0f;

    #pragma unroll 1
    for (int it = 0; it < 8; it++) {
        if (it == 7) cp_wait<0>(); else cp_wait<1>();
        __syncthreads();
        const uint32_t* VHb = (const uint32_t*)(sm + KB_OFF) + (it & 1) * 8704;
        const uint32_t* VLb = VHb + 4352;

        #pragma unroll
        for (int kk = 0; kk < 2; kk++) {
            int ks = kh * 2 + kk;
            int arow = rm * 16 + g;
            int cp0 = it * 64 + ks * 8 + t;
            uint32_t* P0 = (uint32_t*)&S[arow * SSTR];
            uint32_t* P1 = (uint32_t*)&S[(arow + 8) * SSTR];
            uint32_t ah[4] = {P0[cp0], P1[cp0], P0[cp0 + 4], P1[cp0 + 4]};
            uint32_t al[4] = {P0[cp0 + 512], P1[cp0 + 512], P0[cp0 + 516], P1[cp0 + 516]};
            #pragma unroll
            for (int nt = 0; nt < 4; nt++) {
                int rb = (rn * 32 + nt * 8 + g) * 68 + ks * 8 + t;
                uint32_t bh2[2] = {VHb[rb], VHb[rb + 4]};
                uint32_t bl2[2] = {VLb[rb], VLb[rb + 4]};
                mma_bf16(oacc2[nt], ah, bh2);
                mma_bf16(oacc2[nt], ah, bl2);
                mma_bf16(oacc2[nt], al, bh2);
            }
        }
        __syncthreads();
        if (it < 6) issueV(it + 2);
    }

    // ---- combine 4 k-partials (P consumed; reuse S region) ----
    __syncthreads();
    float* Opart = sm;   // 3 buffers of 32x68
    if (kh > 0) {
        float* Ob = Opart + (kh - 1) * 2176;
        #pragma unroll
        for (int nt = 0; nt < 4; nt++) {
            int row = rm * 16 + g, col = rn * 32 + nt * 8 + 2 * t;
            *(float2*)&Ob[row * 68 + col] = make_float2(oacc2[nt][0], oacc2[nt][1]);
            *(float2*)&Ob[(row + 8) * 68 + col] = make_float2(oacc2[nt][2], oacc2[nt][3]);
        }
    }
    __syncthreads();
    if (kh == 0) {
        size_t ob = (size_t)(bh >> 4) * Nn * Ee + (size_t)(bh & 15) * 64;
        #pragma unroll
        for (int nt = 0; nt < 4; nt++) {
            int row = rm * 16 + g, col = rn * 32 + nt * 8 + 2 * t;
            float2 a0 = make_float2(oacc2[nt][0], oacc2[nt][1]);
            float2 a1 = make_float2(oacc2[nt][2], oacc2[nt][3]);
            #pragma unroll
            for (int b = 0; b < 3; b++) {
                float2 p0 = *(float2*)&Opart[b * 2176 + row * 68 + col];
                float2 p1 = *(float2*)&Opart[b * 2176 + (row + 8) * 68 + col];
                a0.x += p0.x; a0.y += p0.y;
                a1.x += p1.x; a1.y += p1.y;
            }
            *(float2*)&out_attn[ob + (size_t)(r0 + row) * Ee + col] = a0;
            *(float2*)&out_attn[ob + (size_t)(r0 + row + 8) * Ee + col] = a1;
        }
    }
}

// ---------------------------------------------------------------------------
extern "C" void kernel_launch(void* const* d_in, const int* in_sizes, int n_in,
                              void* d_out, int out_size) {
    const float* query = (const float*)d_in[0];
    const float* key_  = (const float*)d_in[1];
    const float* value = (const float*)d_in[2];
    const float* ab    = (const float*)d_in[3];
    const float* Wq    = (const float*)d_in[4];
    const float* bq    = (const float*)d_in[5];
    const float* Wk    = (const float*)d_in[6];
    const float* bk    = (const float*)d_in[7];
    const float* Wv    = (const float*)d_in[8];
    const float* bv    = (const float*)d_in[9];

    float* out = (float*)d_out;
    const long long attn_elems = (long long)Bc * Nn * Ee;
    const long long w_elems    = (long long)BHn * Nn * Nn;
    float* attn_out = out;
    float* w_out = nullptr;
    if ((long long)out_size >= attn_elems + w_elems) w_out = out + attn_elems;

    {
        dim3 grid(4096, 6);
        pack_kernel<<<grid, 256>>>(query, key_, value, Wq, Wk, Wv);
    }
    {
        cudaFuncSetAttribute(proj_mma_kernel, cudaFuncAttributeMaxDynamicSharedMemorySize,
                             PROJ_SMEM_BYTES);
        dim3 grid(Mtot / 128, Ee / 128, 3);
        proj_mma_kernel<<<grid, 256, PROJ_SMEM_BYTES>>>(bq, bk, bv);
    }
    {
        dim3 grid(8, 64);
        vt_kernel<<<grid, 256>>>();
    }
    {
        cudaFuncSetAttribute(attn_mma_kernel, cudaFuncAttributeMaxDynamicSharedMemorySize,
                             ATTN_SMEM_BYTES);
        dim3 grid(Nn / 32, BHn);
        attn_mma_kernel<<<grid, 512, ATTN_SMEM_BYTES>>>(ab, attn_out, w_out);
    }
}

// round 8
// speedup vs baseline: 1.2409x; 1.0070x over previous
#include <cuda_runtime.h>
#include <cstdint>

#define Bc   4
#define Nn   1024
#define Ee   1024
#define BHn  64
#define Mtot 4096   // B*N

// Projected Q/K as separate hi/lo bf16x2 planes (pair p covers cols 2p,2p+1).
__device__ uint32_t g_qh[Mtot * 512];
__device__ uint32_t g_ql[Mtot * 512];
__device__ uint32_t g_kh[Mtot * 512];
__device__ uint32_t g_kl[Mtot * 512];
__device__ float    g_v [Mtot * Ee];
// V^T packed planes: [bh][d][cpair]  (64 x 64 x 512)
__device__ uint32_t g_vth[64 * 64 * 512];
__device__ uint32_t g_vtl[64 * 64 * 512];
// Packed GEMM input planes: [z][...]
__device__ uint32_t g_pxh[3][Mtot * 512];
__device__ uint32_t g_pxl[3][Mtot * 512];
__device__ uint32_t g_pwh[3][1024 * 512];
__device__ uint32_t g_pwl[3][1024 * 512];
// Fallback weights buffer if the harness output only holds attn.
__device__ float g_w[(size_t)BHn * Nn * Nn];

// ===========================================================================
// helpers
// ===========================================================================
static __device__ __forceinline__ uint32_t smem_u32(const void* p) {
    uint32_t a;
    asm("{ .reg .u64 t; cvta.to.shared.u64 t, %1; cvt.u32.u64 %0, t; }" : "=r"(a) : "l"(p));
    return a;
}
static __device__ __forceinline__ uint32_t pack_bf16(float x0, float x1) {
    uint32_t r;
    asm("cvt.rn.bf16x2.f32 %0, %1, %2;" : "=r"(r) : "f"(x1), "f"(x0));
    return r;
}
static __device__ __forceinline__ void split2(float x0, float x1, uint32_t& h, uint32_t& l) {
    h = pack_bf16(x0, x1);
    float h0 = __uint_as_float(h << 16);
    float h1 = __uint_as_float(h & 0xFFFF0000u);
    l = pack_bf16(x0 - h0, x1 - h1);
}
static __device__ __forceinline__ void mma_bf16(float* c, const uint32_t* a, const uint32_t* b) {
    asm volatile(
        "mma.sync.aligned.m16n8k16.row.col.f32.bf16.bf16.f32 "
        "{%0,%1,%2,%3}, {%4,%5,%6,%7}, {%8,%9}, {%0,%1,%2,%3};"
        : "+f"(c[0]), "+f"(c[1]), "+f"(c[2]), "+f"(c[3])
        : "r"(a[0]), "r"(a[1]), "r"(a[2]), "r"(a[3]), "r"(b[0]), "r"(b[1]));
}
static __device__ __forceinline__ void cp16(uint32_t dst, const void* src) {
    asm volatile("cp.async.cg.shared.global [%0], [%1], 16;" :: "r"(dst), "l"(src));
}
static __device__ __forceinline__ void cp_commit() {
    asm volatile("cp.async.commit_group;" ::: "memory");
}
template<int N> static __device__ __forceinline__ void cp_wait() {
    asm volatile("cp.async.wait_group %0;" :: "n"(N) : "memory");
}

// ===========================================================================
// Pack kernel: fp32 -> separate hi/lo plane pairs for proj inputs.
// ===========================================================================
__global__ __launch_bounds__(256) void pack_kernel(
    const float* __restrict__ xq, const float* __restrict__ xk, const float* __restrict__ xv,
    const float* __restrict__ wq, const float* __restrict__ wk, const float* __restrict__ wv)
{
    const int z = blockIdx.y;
    const float* src; uint32_t* dh; uint32_t* dl; int nf4;
    switch (z) {
        case 0: src = xq; dh = g_pxh[0]; dl = g_pxl[0]; nf4 = Mtot * 256; break;
        case 1: src = xk; dh = g_pxh[1]; dl = g_pxl[1]; nf4 = Mtot * 256; break;
        case 2: src = xv; dh = g_pxh[2]; dl = g_pxl[2]; nf4 = Mtot * 256; break;
        case 3: src = wq; dh = g_pwh[0]; dl = g_pwl[0]; nf4 = 1024 * 256; break;
        case 4: src = wk; dh = g_pwh[1]; dl = g_pwl[1]; nf4 = 1024 * 256; break;
        default: src = wv; dh = g_pwh[2]; dl = g_pwl[2]; nf4 = 1024 * 256; break;
    }
    int i = blockIdx.x * 256 + threadIdx.x;
    if (i >= nf4) return;
    float4 v = *(const float4*)(src + (size_t)i * 4);
    uint32_t h0, l0, h1, l1;
    split2(v.x, v.y, h0, l0);
    split2(v.z, v.w, h1, l1);
    *(uint2*)&dh[2 * i] = make_uint2(h0, h1);
    *(uint2*)&dl[2 * i] = make_uint2(l0, l1);
}

// ===========================================================================
// Projection GEMM: C = X @ W^T + b, cp.async double-buffered planes.
// Tile 128x128, K-chunk 32 (16 pairs), 256 threads.
// ===========================================================================
#define PSP 36
#define PSTAGE 18432                                // words per stage (4 planes x 128x36)
#define PROJ_SMEM_BYTES ((2 * PSTAGE + 128) * 4)    // 147968

__global__ __launch_bounds__(256, 1) void proj_mma_kernel(
    const float* __restrict__ bq, const float* __restrict__ bk, const float* __restrict__ bv)
{
    extern __shared__ uint32_t psm[];
    float* bsm = (float*)(psm + 2 * PSTAGE);
    const uint32_t smb = smem_u32(psm);

    const int z = blockIdx.z;
    const uint32_t* xh = g_pxh[z]; const uint32_t* xl = g_pxl[z];
    const uint32_t* wh = g_pwh[z]; const uint32_t* wl = g_pwl[z];
    const float* bias = (z == 0) ? bq : (z == 1) ? bk : bv;

    const int tid = threadIdx.x;
    const int w = tid >> 5, lane = tid & 31;
    const int g = lane >> 2, t = lane & 3;
    const int bm = blockIdx.x * 128, bn = blockIdx.y * 128;
    const int wm = w >> 2, wn = w & 3;

    if (tid < 128) bsm[tid] = bias[bn + tid];

    // One k-chunk = 32 k-floats = 16 pairs (words) per row per plane.
    // 4 planes x 128 rows x 4 cp16 (16B each) = 2048 = 256 thr x 8 iters.
    auto issueP = [&](int kc) {
        int st = kc & 1;
        #pragma unroll
        for (int s = 0; s < 8; s++) {
            int idx = tid + 256 * s;          // 0..2047
            int plane = idx >> 9;             // 0 XH, 1 XL, 2 WH, 3 WL
            int row = (idx >> 2) & 127;
            int seg = idx & 3;                // 4 words each
            const uint32_t* src;
            if (plane == 0)      src = xh + (size_t)(bm + row) * 512 + kc * 16 + seg * 4;
            else if (plane == 1) src = xl + (size_t)(bm + row) * 512 + kc * 16 + seg * 4;
            else if (plane == 2) src = wh + (size_t)(bn + row) * 512 + kc * 16 + seg * 4;
            else                 src = wl + (size_t)(bn + row) * 512 + kc * 16 + seg * 4;
            cp16(smb + (uint32_t)(st * PSTAGE + plane * 4608 + row * PSP + seg * 4) * 4, src);
        }
        cp_commit();
    };

    issueP(0);
    issueP(1);

    float acc[4][4][4];
    #pragma unroll
    for (int i = 0; i < 4; i++)
        #pragma unroll
        for (int j = 0; j < 4; j++)
            #pragma unroll
            for (int k = 0; k < 4; k++) acc[i][j][k] = 0.0f;

    #pragma unroll 1
    for (int kc = 0; kc < 32; kc++) {
        if (kc == 31) cp_wait<0>(); else cp_wait<1>();
        __syncthreads();
        const uint32_t* XH = psm + (kc & 1) * PSTAGE;
        const uint32_t* XL = XH + 4608;
        const uint32_t* WH = XH + 9216;
        const uint32_t* WL = XH + 13824;

        #pragma unroll
        for (int ks = 0; ks < 2; ks++) {
            uint32_t bhf[4][2], blf[4][2];
            #pragma unroll
            for (int nt = 0; nt < 4; nt++) {
                int rb = (wn * 32 + nt * 8 + g) * PSP + ks * 8 + t;
                bhf[nt][0] = WH[rb]; bhf[nt][1] = WH[rb + 4];
                blf[nt][0] = WL[rb]; blf[nt][1] = WL[rb + 4];
            }
            #pragma unroll
            for (int mt = 0; mt < 4; mt++) {
                int ra = (wm * 64 + mt * 16 + g) * PSP + ks * 8 + t;
                uint32_t ah[4] = {XH[ra], XH[ra + 8 * PSP], XH[ra + 4], XH[ra + 8 * PSP + 4]};
                uint32_t al[4] = {XL[ra], XL[ra + 8 * PSP], XL[ra + 4], XL[ra + 8 * PSP + 4]};
                #pragma unroll
                for (int nt = 0; nt < 4; nt++) {
                    mma_bf16(acc[mt][nt], ah, bhf[nt]);
                    mma_bf16(acc[mt][nt], ah, blf[nt]);
                    mma_bf16(acc[mt][nt], al, bhf[nt]);
                }
            }
        }
        __syncthreads();
        if (kc < 30) issueP(kc + 2);
    }

    #pragma unroll
    for (int mt = 0; mt < 4; mt++) {
        int row = wm * 64 + mt * 16 + g;
        #pragma unroll
        for (int nt = 0; nt < 4; nt++) {
            int col = wn * 32 + nt * 8 + 2 * t;
            float bx = bsm[col], by = bsm[col + 1];
            float c00 = acc[mt][nt][0] + bx, c01 = acc[mt][nt][1] + by;
            float c10 = acc[mt][nt][2] + bx, c11 = acc[mt][nt][3] + by;
            if (z < 2) {
                uint32_t* dh = (z == 0) ? g_qh : g_kh;
                uint32_t* dl = (z == 0) ? g_ql : g_kl;
                size_t p0 = (size_t)(bm + row) * 512 + ((bn + col) >> 1);
                size_t p1 = (size_t)(bm + row + 8) * 512 + ((bn + col) >> 1);
                uint32_t h, l;
                split2(c00, c01, h, l);
                dh[p0] = h; dl[p0] = l;
                split2(c10, c11, h, l);
                dh[p1] = h; dl[p1] = l;
            } else {
                *(float2*)(g_v + (size_t)(bm + row) * 1024 + bn + col) = make_float2(c00, c01);
                *(float2*)(g_v + (size_t)(bm + row + 8) * 1024 + bn + col) = make_float2(c10, c11);
            }
        }
    }
}

// ===========================================================================
// V transpose+pack: g_v (natural) -> g_vth/g_vtl [bh][d][cpair].
// ===========================================================================
__global__ __launch_bounds__(256) void vt_kernel()
{
    __shared__ uint32_t sh[64 * 65], sl[64 * 65];
    const int bh = blockIdx.y, ct = blockIdx.x, tid = threadIdx.x;

    #pragma unroll
    for (int s = 0; s < 16; s++) {
        int idx = tid + 256 * s;
        int d = idx & 63, cp = idx >> 6;
        const float* p = g_v + (size_t)(ct * 128 + 2 * cp) * 4096 + bh * 64 + d;
        float x0 = p[0], x1 = p[4096];
        uint32_t h, l;
        split2(x0, x1, h, l);
        sh[cp * 65 + d] = h;
        sl[cp * 65 + d] = l;
    }
    __syncthreads();
    #pragma unroll
    for (int s = 0; s < 16; s++) {
        int idx = tid + 256 * s;
        int cp = idx & 63, d = idx >> 6;
        size_t o = ((size_t)(bh * 64 + d) << 9) + ct * 64 + cp;
        g_vth[o] = sh[cp * 65 + d];
        g_vtl[o] = sl[cp * 65 + d];
    }
}

// ===========================================================================
// Attention: register-resident scores. One CTA per (bh, 32 rows), 512 thr.
// ===========================================================================
#define KV_W   0
#define QH_W   18432
#define QL_W   (QH_W + 1152)
#define SCRM_W (QL_W + 1152)     // 20736, 256 words
#define SCRS_W (SCRM_W + 256)    // 20992, 256 words
#define ATTN_SMEM_WORDS 21256
#define ATTN_SMEM_BYTES (ATTN_SMEM_WORDS * 4)   // 85024

__global__ __launch_bounds__(512, 1) void attn_mma_kernel(
    const float* __restrict__ bias, float* __restrict__ out_attn, float* __restrict__ w_out)
{
    extern __shared__ float sm[];
    uint32_t* KV = (uint32_t*)sm + KV_W;
    uint32_t* QH = (uint32_t*)sm + QH_W;
    uint32_t* QL = (uint32_t*)sm + QL_W;
    float* scrM = sm + SCRM_W;
    float* scrS = sm + SCRS_W;
    const uint32_t smb = smem_u32(sm);

    const int tid = threadIdx.x;
    const int w = tid >> 5, lane = tid & 31;
    const int g = lane >> 2, t = lane & 3;
    const int wm = w >> 3, wn = w & 7;
    const int m0 = wm * 16, n0 = wn * 16;
    const int bh = blockIdx.y;
    const int r0 = blockIdx.x * 32;

    const float* bsrc = bias + (size_t)(bh & 3) * Nn * Nn;
    float* wbase = (w_out != nullptr) ? w_out : g_w;
    float* wrow_base = wbase + (size_t)bh * Nn * Nn;

    auto issueK = [&](int it) {
        int b = it & 1;
        #pragma unroll
        for (int s = 0; s < 4; s++) {
            int idx = tid + 512 * s;
            int plane = idx >> 10;
            int row = (idx >> 3) & 127;
            int seg = idx & 7;
            const uint32_t* src = (plane ? g_kl : g_kh) +
                (size_t)(it * 128 + row) * 2048 + bh * 32 + seg * 4;
            cp16(smb + (uint32_t)(KV_W + b * 9216 + plane * 4608 + row * 36 + seg * 4) * 4, src);
        }
        cp_commit();
    };
    auto issueV = [&](int it) {
        int b = it & 1;
        #pragma unroll
        for (int s = 0; s < 4; s++) {
            int idx = tid + 512 * s;
            int plane = idx >> 10;
            int row = (idx >> 4) & 63;
            int seg = idx & 15;
            const uint32_t* src = (plane ? g_vtl : g_vth) +
                (((size_t)(bh * 64 + row)) << 9) + it * 64 + seg * 4;
            cp16(smb + (uint32_t)(KV_W + b * 8704 + plane * 4352 + row * 68 + seg * 4) * 4, src);
        }
        cp_commit();
    };

    // ---- prologue: Q, K0, K1 ----
    {
        int plane = tid >> 8, ci = tid & 255, row = ci >> 3, seg = ci & 7;
        const uint32_t* src = (plane ? g_ql : g_qh) +
            (size_t)(r0 + row) * 2048 + bh * 32 + seg * 4;
        cp16(smb + (uint32_t)((plane ? QL_W : QH_W) + row * 36 + seg * 4) * 4, src);
        cp_commit();
    }
    issueK(0);
    issueK(1);

    cp_wait<2>();
    __syncthreads();
    uint32_t qah[4][4], qal[4][4];
    #pragma unroll
    for (int ks = 0; ks < 4; ks++) {
        int ra = (m0 + g) * 36 + ks * 8 + t;
        qah[ks][0] = QH[ra];     qah[ks][1] = QH[ra + 288];
        qah[ks][2] = QH[ra + 4]; qah[ks][3] = QH[ra + 292];
        qal[ks][0] = QL[ra];     qal[ks][1] = QL[ra + 288];
        qal[ks][2] = QL[ra + 4]; qal[ks][3] = QL[ra + 292];
    }

    // ---- scores into registers (64 floats/thread) ----
    float sv[64];
    #pragma unroll
    for (int j = 0; j < 64; j++) sv[j] = 0.0f;

    const int rowg = r0 + m0 + g;

    #pragma unroll
    for (int it = 0; it < 8; it++) {
        if (it == 7) cp_wait<0>(); else cp_wait<1>();
        __syncthreads();
        const uint32_t* KHb = KV + (it & 1) * 9216;
        const uint32_t* KLb = KHb + 4608;
        float* s = sv + it * 8;

        #pragma unroll
        for (int ks = 0; ks < 4; ks++) {
            int rb0 = (n0 + g) * 36 + ks * 8 + t;
            int rb1 = (n0 + 8 + g) * 36 + ks * 8 + t;
            uint32_t bh0[2] = {KHb[rb0], KHb[rb0 + 4]};
            uint32_t bl0[2] = {KLb[rb0], KLb[rb0 + 4]};
            uint32_t bh1[2] = {KHb[rb1], KHb[rb1 + 4]};
            uint32_t bl1[2] = {KLb[rb1], KLb[rb1 + 4]};
            mma_bf16(s,     qah[ks], bh0);
            mma_bf16(s,     qah[ks], bl0);
            mma_bf16(s,     qal[ks], bh0);
            mma_bf16(s + 4, qah[ks], bh1);
            mma_bf16(s + 4, qah[ks], bl1);
            mma_bf16(s + 4, qal[ks], bh1);
        }
        {
            int c0 = it * 128 + n0 + 2 * t;
            int c1 = c0 + 8;
            float2 b00 = *(const float2*)(bsrc + (size_t)rowg * 1024 + c0);
            float2 b01 = *(const float2*)(bsrc + (size_t)(rowg + 8) * 1024 + c0);
            float2 b10 = *(const float2*)(bsrc + (size_t)rowg * 1024 + c1);
            float2 b11 = *(const float2*)(bsrc + (size_t)(rowg + 8) * 1024 + c1);
            s[0] += b00.x; s[1] += b00.y;
            s[2] += b01.x; s[3] += b01.y;
            s[4] += b10.x; s[5] += b10.y;
            s[6] += b11.x; s[7] += b11.y;
        }
        __syncthreads();
        if (it < 6) issueK(it + 2);
    }

    // ---- V pipeline prologue (overlaps softmax) ----
    issueV(0);
    issueV(1);

    // ---- softmax: quad shuffle + cross-warp smem reduce ----
    float mg = -3.0e38f, mg8 = -3.0e38f;
    #pragma unroll
    for (int it = 0; it < 8; it++) {
        float* s = sv + it * 8;
        mg  = fmaxf(mg,  fmaxf(fmaxf(s[0], s[1]), fmaxf(s[4], s[5])));
        mg8 = fmaxf(mg8, fmaxf(fmaxf(s[2], s[3]), fmaxf(s[6], s[7])));
    }
    mg  = fmaxf(mg,  __shfl_xor_sync(0xffffffffu, mg, 1));
    mg  = fmaxf(mg,  __shfl_xor_sync(0xffffffffu, mg, 2));
    mg8 = fmaxf(mg8, __shfl_xor_sync(0xffffffffu, mg8, 1));
    mg8 = fmaxf(mg8, __shfl_xor_sync(0xffffffffu, mg8, 2));
    if (t == 0) {
        scrM[(m0 + g) * 8 + wn]     = mg;
        scrM[(m0 + g + 8) * 8 + wn] = mg8;
    }
    __syncthreads();
    float Mg = -3.0e38f, Mg8 = -3.0e38f;
    #pragma unroll
    for (int k = 0; k < 8; k++) {
        Mg  = fmaxf(Mg,  scrM[(m0 + g) * 8 + k]);
        Mg8 = fmaxf(Mg8, scrM[(m0 + g + 8) * 8 + k]);
    }
    float sg = 0.0f, sg8 = 0.0f;
    #pragma unroll
    for (int it = 0; it < 8; it++) {
        float* s = sv + it * 8;
        s[0] = __expf(s[0] - Mg);  s[1] = __expf(s[1] - Mg);
        s[4] = __expf(s[4] - Mg);  s[5] = __expf(s[5] - Mg);
        s[2] = __expf(s[2] - Mg8); s[3] = __expf(s[3] - Mg8);
        s[6] = __expf(s[6] - Mg8); s[7] = __expf(s[7] - Mg8);
        sg  += s[0] + s[1] + s[4] + s[5];
        sg8 += s[2] + s[3] + s[6] + s[7];
    }
    sg  += __shfl_xor_sync(0xffffffffu, sg, 1);
    sg  += __shfl_xor_sync(0xffffffffu, sg, 2);
    sg8 += __shfl_xor_sync(0xffffffffu, sg8, 1);
    sg8 += __shfl_xor_sync(0xffffffffu, sg8, 2);
    if (t == 0) {
        scrS[(m0 + g) * 8 + wn]     = sg;
        scrS[(m0 + g + 8) * 8 + wn] = sg8;
    }
    __syncthreads();
    float Sg = 0.0f, Sg8 = 0.0f;
    #pragma unroll
    for (int k = 0; k < 8; k++) {
        Sg  += scrS[(m0 + g) * 8 + k];
        Sg8 += scrS[(m0 + g + 8) * 8 + k];
    }
    const float invg = 1.0f / Sg, invg8 = 1.0f / Sg8;

    // ---- scale, store weights, pack P into register A-fragments ----
    uint32_t pah[8][4], pal[8][4];
    float* wr0 = wrow_base + (size_t)rowg * 1024;
    float* wr8 = wrow_base + (size_t)(rowg + 8) * 1024;
    #pragma unroll
    for (int it = 0; it < 8; it++) {
        float* s = sv + it * 8;
        float p0 = s[0] * invg,  p1 = s[1] * invg;
        float p2 = s[2] * invg8, p3 = s[3] * invg8;
        float p4 = s[4] * invg,  p5 = s[5] * invg;
        float p6 = s[6] * invg8, p7 = s[7] * invg8;
        int c0 = it * 128 + n0 + 2 * t;
        *(float2*)&wr0[c0]     = make_float2(p0, p1);
        *(float2*)&wr8[c0]     = make_float2(p2, p3);
        *(float2*)&wr0[c0 + 8] = make_float2(p4, p5);
        *(float2*)&wr8[c0 + 8] = make_float2(p6, p7);
        split2(p0, p1, pah[it][0], pal[it][0]);
        split2(p2, p3, pah[it][1], pal[it][1]);
        split2(p4, p5, pah[it][2], pal[it][2]);
        split2(p6, p7, pah[it][3], pal[it][3]);
    }

    // ---- AV: each warp covers its 128 c-cols (k), partial O 16x64 ----
    float oacc[8][4];
    #pragma unroll
    for (int i = 0; i < 8; i++)
        #pragma unroll
        for (int j = 0; j < 4; j++) oacc[i][j] = 0.0f;

    #pragma unroll
    for (int it = 0; it < 8; it++) {
        if (it == 7) cp_wait<0>(); else cp_wait<1>();
        __syncthreads();
        const uint32_t* VHb = KV + (it & 1) * 8704;
        const uint32_t* VLb = VHb + 4352;

        #pragma unroll
        for (int nt = 0; nt < 8; nt++) {
            int rb = (nt * 8 + g) * 68 + wn * 8 + t;
            uint32_t bh2[2] = {VHb[rb], VHb[rb + 4]};
            uint32_t bl2[2] = {VLb[rb], VLb[rb + 4]};
            mma_bf16(oacc[nt], pah[it], bh2);
            mma_bf16(oacc[nt], pah[it], bl2);
            mma_bf16(oacc[nt], pal[it], bh2);
        }
        __syncthreads();
        if (it < 6) issueV(it + 2);
    }

    // ---- tree-reduce 8 wn-partials (overlay on KV region) ----
    float* red = sm + KV_W;
    auto stPart = [&](int b) {
        int base = b * 2176 + wm * 1088;
        #pragma unroll
        for (int nt = 0; nt < 8; nt++) {
            *(float2*)&red[base + g * 66 + nt * 8 + 2 * t] =
                make_float2(oacc[nt][0], oacc[nt][1]);
            *(float2*)&red[base + (g + 8) * 66 + nt * 8 + 2 * t] =
                make_float2(oacc[nt][2], oacc[nt][3]);
        }
    };
    auto addPart = [&](int b) {
        int base = b * 2176 + wm * 1088;
        #pragma unroll
        for (int nt = 0; nt < 8; nt++) {
            float2 p0 = *(float2*)&red[base + g * 66 + nt * 8 + 2 * t];
            float2 p1 = *(float2*)&red[base + (g + 8) * 66 + nt * 8 + 2 * t];
            oacc[nt][0] += p0.x; oacc[nt][1] += p0.y;
            oacc[nt][2] += p1.x; oacc[nt][3] += p1.y;
        }
    };
    if (wn >= 4) stPart(wn - 4);
    __syncthreads();
    if (wn < 4) addPart(wn);
    __syncthreads();
    if (wn == 2 || wn == 3) stPart(wn - 2);
    __syncthreads();
    if (wn < 2) addPart(wn);
    __syncthreads();
    if (wn == 1) stPart(0);
    __syncthreads();
    if (wn == 0) {
        addPart(0);
        size_t ob = (size_t)(bh >> 4) * Nn * Ee + (size_t)(bh & 15) * 64;
        #pragma unroll
        for (int nt = 0; nt < 8; nt++) {
            int col = nt * 8 + 2 * t;
            *(float2*)&out_attn[ob + (size_t)rowg * Ee + col] =
                make_float2(oacc[nt][0], oacc[nt][1]);
            *(float2*)&out_attn[ob + (size_t)(rowg + 8) * Ee + col] =
                make_float2(oacc[nt][2], oacc[nt][3]);
        }
    }
}

// ---------------------------------------------------------------------------
extern "C" void kernel_launch(void* const* d_in, const int* in_sizes, int n_in,
                              void* d_out, int out_size) {
    const float* query = (const float*)d_in[0];
    const float* key_  = (const float*)d_in[1];
    const float* value = (const float*)d_in[2];
    const float* ab    = (const float*)d_in[3];
    const float* Wq    = (const float*)d_in[4];
    const float* bq    = (const float*)d_in[5];
    const float* Wk    = (const float*)d_in[6];
    const float* bk    = (const float*)d_in[7];
    const float* Wv    = (const float*)d_in[8];
    const float* bv    = (const float*)d_in[9];

    float* out = (float*)d_out;
    const long long attn_elems = (long long)Bc * Nn * Ee;
    const long long w_elems    = (long long)BHn * Nn * Nn;
    float* attn_out = out;
    float* w_out = nullptr;
    if ((long long)out_size >= attn_elems + w_elems) w_out = out + attn_elems;

    {
        dim3 grid(4096, 6);
        pack_kernel<<<grid, 256>>>(query, key_, value, Wq, Wk, Wv);
    }
    {
        cudaFuncSetAttribute(proj_mma_kernel, cudaFuncAttributeMaxDynamicSharedMemorySize,
                             PROJ_SMEM_BYTES);
        dim3 grid(Mtot / 128, Ee / 128, 3);
        proj_mma_kernel<<<grid, 256, PROJ_SMEM_BYTES>>>(bq, bk, bv);
    }
    {
        dim3 grid(8, 64);
        vt_kernel<<<grid, 256>>>();
    }
    {
        cudaFuncSetAttribute(attn_mma_kernel, cudaFuncAttributeMaxDynamicSharedMemorySize,
                             ATTN_SMEM_BYTES);
        dim3 grid(Nn / 32, BHn);
        attn_mma_kernel<<<grid, 512, ATTN_SMEM_BYTES>>>(ab, attn_out, w_out);
    }
}

// round 9
// speedup vs baseline: 1.2607x; 1.0160x over previous
#include <cuda_runtime.h>
#include <cstdint>

#define Bc   4
#define Nn   1024
#define Ee   1024
#define BHn  64
#define Mtot 4096   // B*N

// Projected Q/K as separate hi/lo bf16x2 planes (pair p covers cols 2p,2p+1).
__device__ uint32_t g_qh[Mtot * 512];
__device__ uint32_t g_ql[Mtot * 512];
__device__ uint32_t g_kh[Mtot * 512];
__device__ uint32_t g_kl[Mtot * 512];
__device__ float    g_v [Mtot * Ee];
// V^T packed planes: [bh][d][cpair]  (64 x 64 x 512)
__device__ uint32_t g_vth[64 * 64 * 512];
__device__ uint32_t g_vtl[64 * 64 * 512];
// Packed GEMM input planes: [z][...]
__device__ uint32_t g_pxh[3][Mtot * 512];
__device__ uint32_t g_pxl[3][Mtot * 512];
__device__ uint32_t g_pwh[3][1024 * 512];
__device__ uint32_t g_pwl[3][1024 * 512];
// Fallback weights buffer if the harness output only holds attn.
__device__ float g_w[(size_t)BHn * Nn * Nn];

// ===========================================================================
// helpers
// ===========================================================================
static __device__ __forceinline__ uint32_t smem_u32(const void* p) {
    uint32_t a;
    asm("{ .reg .u64 t; cvta.to.shared.u64 t, %1; cvt.u32.u64 %0, t; }" : "=r"(a) : "l"(p));
    return a;
}
static __device__ __forceinline__ uint32_t pack_bf16(float x0, float x1) {
    uint32_t r;
    asm("cvt.rn.bf16x2.f32 %0, %1, %2;" : "=r"(r) : "f"(x1), "f"(x0));
    return r;
}
static __device__ __forceinline__ void split2(float x0, float x1, uint32_t& h, uint32_t& l) {
    h = pack_bf16(x0, x1);
    float h0 = __uint_as_float(h << 16);
    float h1 = __uint_as_float(h & 0xFFFF0000u);
    l = pack_bf16(x0 - h0, x1 - h1);
}
static __device__ __forceinline__ void mma_bf16(float* c, const uint32_t* a, const uint32_t* b) {
    asm volatile(
        "mma.sync.aligned.m16n8k16.row.col.f32.bf16.bf16.f32 "
        "{%0,%1,%2,%3}, {%4,%5,%6,%7}, {%8,%9}, {%0,%1,%2,%3};"
        : "+f"(c[0]), "+f"(c[1]), "+f"(c[2]), "+f"(c[3])
        : "r"(a[0]), "r"(a[1]), "r"(a[2]), "r"(a[3]), "r"(b[0]), "r"(b[1]));
}
static __device__ __forceinline__ void cp16(uint32_t dst, const void* src) {
    asm volatile("cp.async.cg.shared.global [%0], [%1], 16;" :: "r"(dst), "l"(src));
}
static __device__ __forceinline__ void cp_commit() {
    asm volatile("cp.async.commit_group;" ::: "memory");
}
template<int N> static __device__ __forceinline__ void cp_wait() {
    asm volatile("cp.async.wait_group %0;" :: "n"(N) : "memory");
}

// ===========================================================================
// Pack kernel: fp32 -> separate hi/lo plane pairs for proj inputs.
// ===========================================================================
__global__ __launch_bounds__(256) void pack_kernel(
    const float* __restrict__ xq, const float* __restrict__ xk, const float* __restrict__ xv,
    const float* __restrict__ wq, const float* __restrict__ wk, const float* __restrict__ wv)
{
    const int z = blockIdx.y;
    const float* src; uint32_t* dh; uint32_t* dl; int nf4;
    switch (z) {
        case 0: src = xq; dh = g_pxh[0]; dl = g_pxl[0]; nf4 = Mtot * 256; break;
        case 1: src = xk; dh = g_pxh[1]; dl = g_pxl[1]; nf4 = Mtot * 256; break;
        case 2: src = xv; dh = g_pxh[2]; dl = g_pxl[2]; nf4 = Mtot * 256; break;
        case 3: src = wq; dh = g_pwh[0]; dl = g_pwl[0]; nf4 = 1024 * 256; break;
        case 4: src = wk; dh = g_pwh[1]; dl = g_pwl[1]; nf4 = 1024 * 256; break;
        default: src = wv; dh = g_pwh[2]; dl = g_pwl[2]; nf4 = 1024 * 256; break;
    }
    int i = blockIdx.x * 256 + threadIdx.x;
    if (i >= nf4) return;
    float4 v = *(const float4*)(src + (size_t)i * 4);
    uint32_t h0, l0, h1, l1;
    split2(v.x, v.y, h0, l0);
    split2(v.z, v.w, h1, l1);
    *(uint2*)&dh[2 * i] = make_uint2(h0, h1);
    *(uint2*)&dl[2 * i] = make_uint2(l0, l1);
}

// ===========================================================================
// Projection GEMM: C = X @ W^T + b, cp.async double-buffered planes.
// ===========================================================================
#define PSP 36
#define PSTAGE 18432
#define PROJ_SMEM_BYTES ((2 * PSTAGE + 128) * 4)    // 147968

__global__ __launch_bounds__(256, 1) void proj_mma_kernel(
    const float* __restrict__ bq, const float* __restrict__ bk, const float* __restrict__ bv)
{
    extern __shared__ uint32_t psm[];
    float* bsm = (float*)(psm + 2 * PSTAGE);
    const uint32_t smb = smem_u32(psm);

    const int z = blockIdx.z;
    const uint32_t* xh = g_pxh[z]; const uint32_t* xl = g_pxl[z];
    const uint32_t* wh = g_pwh[z]; const uint32_t* wl = g_pwl[z];
    const float* bias = (z == 0) ? bq : (z == 1) ? bk : bv;

    const int tid = threadIdx.x;
    const int w = tid >> 5, lane = tid & 31;
    const int g = lane >> 2, t = lane & 3;
    const int bm = blockIdx.x * 128, bn = blockIdx.y * 128;
    const int wm = w >> 2, wn = w & 3;

    if (tid < 128) bsm[tid] = bias[bn + tid];

    auto issueP = [&](int kc) {
        int st = kc & 1;
        #pragma unroll
        for (int s = 0; s < 8; s++) {
            int idx = tid + 256 * s;          // 0..2047
            int plane = idx >> 9;
            int row = (idx >> 2) & 127;
            int seg = idx & 3;
            const uint32_t* src;
            if (plane == 0)      src = xh + (size_t)(bm + row) * 512 + kc * 16 + seg * 4;
            else if (plane == 1) src = xl + (size_t)(bm + row) * 512 + kc * 16 + seg * 4;
            else if (plane == 2) src = wh + (size_t)(bn + row) * 512 + kc * 16 + seg * 4;
            else                 src = wl + (size_t)(bn + row) * 512 + kc * 16 + seg * 4;
            cp16(smb + (uint32_t)(st * PSTAGE + plane * 4608 + row * PSP + seg * 4) * 4, src);
        }
        cp_commit();
    };

    issueP(0);
    issueP(1);

    float acc[4][4][4];
    #pragma unroll
    for (int i = 0; i < 4; i++)
        #pragma unroll
        for (int j = 0; j < 4; j++)
            #pragma unroll
            for (int k = 0; k < 4; k++) acc[i][j][k] = 0.0f;

    #pragma unroll 1
    for (int kc = 0; kc < 32; kc++) {
        if (kc == 31) cp_wait<0>(); else cp_wait<1>();
        __syncthreads();
        const uint32_t* XH = psm + (kc & 1) * PSTAGE;
        const uint32_t* XL = XH + 4608;
        const uint32_t* WH = XH + 9216;
        const uint32_t* WL = XH + 13824;

        #pragma unroll
        for (int ks = 0; ks < 2; ks++) {
            uint32_t bhf[4][2], blf[4][2];
            #pragma unroll
            for (int nt = 0; nt < 4; nt++) {
                int rb = (wn * 32 + nt * 8 + g) * PSP + ks * 8 + t;
                bhf[nt][0] = WH[rb]; bhf[nt][1] = WH[rb + 4];
                blf[nt][0] = WL[rb]; blf[nt][1] = WL[rb + 4];
            }
            #pragma unroll
            for (int mt = 0; mt < 4; mt++) {
                int ra = (wm * 64 + mt * 16 + g) * PSP + ks * 8 + t;
                uint32_t ah[4] = {XH[ra], XH[ra + 8 * PSP], XH[ra + 4], XH[ra + 8 * PSP + 4]};
                uint32_t al[4] = {XL[ra], XL[ra + 8 * PSP], XL[ra + 4], XL[ra + 8 * PSP + 4]};
                #pragma unroll
                for (int nt = 0; nt < 4; nt++) {
                    mma_bf16(acc[mt][nt], ah, bhf[nt]);
                    mma_bf16(acc[mt][nt], ah, blf[nt]);
                    mma_bf16(acc[mt][nt], al, bhf[nt]);
                }
            }
        }
        __syncthreads();
        if (kc < 30) issueP(kc + 2);
    }

    #pragma unroll
    for (int mt = 0; mt < 4; mt++) {
        int row = wm * 64 + mt * 16 + g;
        #pragma unroll
        for (int nt = 0; nt < 4; nt++) {
            int col = wn * 32 + nt * 8 + 2 * t;
            float bx = bsm[col], by = bsm[col + 1];
            float c00 = acc[mt][nt][0] + bx, c01 = acc[mt][nt][1] + by;
            float c10 = acc[mt][nt][2] + bx, c11 = acc[mt][nt][3] + by;
            if (z < 2) {
                uint32_t* dh = (z == 0) ? g_qh : g_kh;
                uint32_t* dl = (z == 0) ? g_ql : g_kl;
                size_t p0 = (size_t)(bm + row) * 512 + ((bn + col) >> 1);
                size_t p1 = (size_t)(bm + row + 8) * 512 + ((bn + col) >> 1);
                uint32_t h, l;
                split2(c00, c01, h, l);
                dh[p0] = h; dl[p0] = l;
                split2(c10, c11, h, l);
                dh[p1] = h; dl[p1] = l;
            } else {
                *(float2*)(g_v + (size_t)(bm + row) * 1024 + bn + col) = make_float2(c00, c01);
                *(float2*)(g_v + (size_t)(bm + row + 8) * 1024 + bn + col) = make_float2(c10, c11);
            }
        }
    }
}

// ===========================================================================
// V transpose+pack: g_v (natural) -> g_vth/g_vtl [bh][d][cpair].
// ===========================================================================
__global__ __launch_bounds__(256) void vt_kernel()
{
    __shared__ uint32_t sh[64 * 65], sl[64 * 65];
    const int bh = blockIdx.y, ct = blockIdx.x, tid = threadIdx.x;

    #pragma unroll
    for (int s = 0; s < 16; s++) {
        int idx = tid + 256 * s;
        int d = idx & 63, cp = idx >> 6;
        const float* p = g_v + (size_t)(ct * 128 + 2 * cp) * 4096 + bh * 64 + d;
        float x0 = p[0], x1 = p[4096];
        uint32_t h, l;
        split2(x0, x1, h, l);
        sh[cp * 65 + d] = h;
        sl[cp * 65 + d] = l;
    }
    __syncthreads();
    #pragma unroll
    for (int s = 0; s < 16; s++) {
        int idx = tid + 256 * s;
        int cp = idx & 63, d = idx >> 6;
        size_t o = ((size_t)(bh * 64 + d) << 9) + ct * 64 + cp;
        g_vth[o] = sh[cp * 65 + d];
        g_vtl[o] = sl[cp * 65 + d];
    }
}

// ===========================================================================
// Attention: register-resident scores; P packed per-tile inside AV loop.
// ===========================================================================
#define KV_W   0
#define QH_W   18432
#define QL_W   (QH_W + 1152)
#define SCRM_W (QL_W + 1152)
#define SCRS_W (SCRM_W + 256)
#define ATTN_SMEM_WORDS 21256
#define ATTN_SMEM_BYTES (ATTN_SMEM_WORDS * 4)   // 85024

__global__ __launch_bounds__(512, 1) void attn_mma_kernel(
    const float* __restrict__ bias, float* __restrict__ out_attn, float* __restrict__ w_out)
{
    extern __shared__ float sm[];
    uint32_t* KV = (uint32_t*)sm + KV_W;
    uint32_t* QH = (uint32_t*)sm + QH_W;
    uint32_t* QL = (uint32_t*)sm + QL_W;
    float* scrM = sm + SCRM_W;
    float* scrS = sm + SCRS_W;
    const uint32_t smb = smem_u32(sm);

    const int tid = threadIdx.x;
    const int w = tid >> 5, lane = tid & 31;
    const int g = lane >> 2, t = lane & 3;
    const int wm = w >> 3, wn = w & 7;
    const int m0 = wm * 16, n0 = wn * 16;
    const int bh = blockIdx.y;
    const int r0 = blockIdx.x * 32;

    const float* bsrc = bias + (size_t)(bh & 3) * Nn * Nn;
    float* wbase = (w_out != nullptr) ? w_out : g_w;
    float* wrow_base = wbase + (size_t)bh * Nn * Nn;

    auto issueK = [&](int it) {
        int b = it & 1;
        #pragma unroll
        for (int s = 0; s < 4; s++) {
            int idx = tid + 512 * s;
            int plane = idx >> 10;
            int row = (idx >> 3) & 127;
            int seg = idx & 7;
            const uint32_t* src = (plane ? g_kl : g_kh) +
                (size_t)(it * 128 + row) * 2048 + bh * 32 + seg * 4;
            cp16(smb + (uint32_t)(KV_W + b * 9216 + plane * 4608 + row * 36 + seg * 4) * 4, src);
        }
        cp_commit();
    };
    auto issueV = [&](int it) {
        int b = it & 1;
        #pragma unroll
        for (int s = 0; s < 4; s++) {
            int idx = tid + 512 * s;
            int plane = idx >> 10;
            int row = (idx >> 4) & 63;
            int seg = idx & 15;
            const uint32_t* src = (plane ? g_vtl : g_vth) +
                (((size_t)(bh * 64 + row)) << 9) + it * 64 + seg * 4;
            cp16(smb + (uint32_t)(KV_W + b * 8704 + plane * 4352 + row * 68 + seg * 4) * 4, src);
        }
        cp_commit();
    };

    // ---- prologue: Q, K0, K1 ----
    {
        int plane = tid >> 8, ci = tid & 255, row = ci >> 3, seg = ci & 7;
        const uint32_t* src = (plane ? g_ql : g_qh) +
            (size_t)(r0 + row) * 2048 + bh * 32 + seg * 4;
        cp16(smb + (uint32_t)((plane ? QL_W : QH_W) + row * 36 + seg * 4) * 4, src);
        cp_commit();
    }
    issueK(0);
    issueK(1);

    cp_wait<2>();
    __syncthreads();
    uint32_t qah[4][4], qal[4][4];
    #pragma unroll
    for (int ks = 0; ks < 4; ks++) {
        int ra = (m0 + g) * 36 + ks * 8 + t;
        qah[ks][0] = QH[ra];     qah[ks][1] = QH[ra + 288];
        qah[ks][2] = QH[ra + 4]; qah[ks][3] = QH[ra + 292];
        qal[ks][0] = QL[ra];     qal[ks][1] = QL[ra + 288];
        qal[ks][2] = QL[ra + 4]; qal[ks][3] = QL[ra + 292];
    }

    // ---- scores into registers (64 floats/thread) ----
    float sv[64];
    #pragma unroll
    for (int j = 0; j < 64; j++) sv[j] = 0.0f;

    const int rowg = r0 + m0 + g;

    #pragma unroll
    for (int it = 0; it < 8; it++) {
        if (it == 7) cp_wait<0>(); else cp_wait<1>();
        __syncthreads();
        const uint32_t* KHb = KV + (it & 1) * 9216;
        const uint32_t* KLb = KHb + 4608;
        float* s = sv + it * 8;

        #pragma unroll
        for (int ks = 0; ks < 4; ks++) {
            int rb0 = (n0 + g) * 36 + ks * 8 + t;
            int rb1 = (n0 + 8 + g) * 36 + ks * 8 + t;
            uint32_t bh0[2] = {KHb[rb0], KHb[rb0 + 4]};
            uint32_t bl0[2] = {KLb[rb0], KLb[rb0 + 4]};
            uint32_t bh1[2] = {KHb[rb1], KHb[rb1 + 4]};
            uint32_t bl1[2] = {KLb[rb1], KLb[rb1 + 4]};
            mma_bf16(s,     qah[ks], bh0);
            mma_bf16(s,     qah[ks], bl0);
            mma_bf16(s,     qal[ks], bh0);
            mma_bf16(s + 4, qah[ks], bh1);
            mma_bf16(s + 4, qah[ks], bl1);
            mma_bf16(s + 4, qal[ks], bh1);
        }
        {
            int c0 = it * 128 + n0 + 2 * t;
            int c1 = c0 + 8;
            float2 b00 = *(const float2*)(bsrc + (size_t)rowg * 1024 + c0);
            float2 b01 = *(const float2*)(bsrc + (size_t)(rowg + 8) * 1024 + c0);
            float2 b10 = *(const float2*)(bsrc + (size_t)rowg * 1024 + c1);
            float2 b11 = *(const float2*)(bsrc + (size_t)(rowg + 8) * 1024 + c1);
            s[0] += b00.x; s[1] += b00.y;
            s[2] += b01.x; s[3] += b01.y;
            s[4] += b10.x; s[5] += b10.y;
            s[6] += b11.x; s[7] += b11.y;
        }
        __syncthreads();
        if (it < 6) issueK(it + 2);
    }

    // ---- V pipeline prologue (overlaps softmax) ----
    issueV(0);
    issueV(1);

    // ---- softmax: quad shuffle + cross-warp smem reduce ----
    float mg = -3.0e38f, mg8 = -3.0e38f;
    #pragma unroll
    for (int it = 0; it < 8; it++) {
        float* s = sv + it * 8;
        mg  = fmaxf(mg,  fmaxf(fmaxf(s[0], s[1]), fmaxf(s[4], s[5])));
        mg8 = fmaxf(mg8, fmaxf(fmaxf(s[2], s[3]), fmaxf(s[6], s[7])));
    }
    mg  = fmaxf(mg,  __shfl_xor_sync(0xffffffffu, mg, 1));
    mg  = fmaxf(mg,  __shfl_xor_sync(0xffffffffu, mg, 2));
    mg8 = fmaxf(mg8, __shfl_xor_sync(0xffffffffu, mg8, 1));
    mg8 = fmaxf(mg8, __shfl_xor_sync(0xffffffffu, mg8, 2));
    if (t == 0) {
        scrM[(m0 + g) * 8 + wn]     = mg;
        scrM[(m0 + g + 8) * 8 + wn] = mg8;
    }
    __syncthreads();
    float Mg = -3.0e38f, Mg8 = -3.0e38f;
    #pragma unroll
    for (int k = 0; k < 8; k++) {
        Mg  = fmaxf(Mg,  scrM[(m0 + g) * 8 + k]);
        Mg8 = fmaxf(Mg8, scrM[(m0 + g + 8) * 8 + k]);
    }
    float sg = 0.0f, sg8 = 0.0f;
    #pragma unroll
    for (int it = 0; it < 8; it++) {
        float* s = sv + it * 8;
        s[0] = __expf(s[0] - Mg);  s[1] = __expf(s[1] - Mg);
        s[4] = __expf(s[4] - Mg);  s[5] = __expf(s[5] - Mg);
        s[2] = __expf(s[2] - Mg8); s[3] = __expf(s[3] - Mg8);
        s[6] = __expf(s[6] - Mg8); s[7] = __expf(s[7] - Mg8);
        sg  += s[0] + s[1] + s[4] + s[5];
        sg8 += s[2] + s[3] + s[6] + s[7];
    }
    sg  += __shfl_xor_sync(0xffffffffu, sg, 1);
    sg  += __shfl_xor_sync(0xffffffffu, sg, 2);
    sg8 += __shfl_xor_sync(0xffffffffu, sg8, 1);
    sg8 += __shfl_xor_sync(0xffffffffu, sg8, 2);
    if (t == 0) {
        scrS[(m0 + g) * 8 + wn]     = sg;
        scrS[(m0 + g + 8) * 8 + wn] = sg8;
    }
    __syncthreads();
    float Sg = 0.0f, Sg8 = 0.0f;
    #pragma unroll
    for (int k = 0; k < 8; k++) {
        Sg  += scrS[(m0 + g) * 8 + k];
        Sg8 += scrS[(m0 + g + 8) * 8 + k];
    }
    const float invg = 1.0f / Sg, invg8 = 1.0f / Sg8;

    // ---- AV loop: per-tile P scale + weights-store + pack + MMA ----
    float* wr0 = wrow_base + (size_t)rowg * 1024;
    float* wr8 = wrow_base + (size_t)(rowg + 8) * 1024;

    float oacc[8][4];
    #pragma unroll
    for (int i = 0; i < 8; i++)
        #pragma unroll
        for (int j = 0; j < 4; j++) oacc[i][j] = 0.0f;

    #pragma unroll
    for (int it = 0; it < 8; it++) {
        if (it == 7) cp_wait<0>(); else cp_wait<1>();
        __syncthreads();
        const uint32_t* VHb = KV + (it & 1) * 8704;
        const uint32_t* VLb = VHb + 4352;

        // scale scores -> P, store weights, pack A-fragments (transient regs)
        float* s = sv + it * 8;
        float p0 = s[0] * invg,  p1 = s[1] * invg;
        float p2 = s[2] * invg8, p3 = s[3] * invg8;
        float p4 = s[4] * invg,  p5 = s[5] * invg;
        float p6 = s[6] * invg8, p7 = s[7] * invg8;
        int c0 = it * 128 + n0 + 2 * t;
        *(float2*)&wr0[c0]     = make_float2(p0, p1);
        *(float2*)&wr8[c0]     = make_float2(p2, p3);
        *(float2*)&wr0[c0 + 8] = make_float2(p4, p5);
        *(float2*)&wr8[c0 + 8] = make_float2(p6, p7);
        uint32_t pah[4], pal[4];
        split2(p0, p1, pah[0], pal[0]);
        split2(p2, p3, pah[1], pal[1]);
        split2(p4, p5, pah[2], pal[2]);
        split2(p6, p7, pah[3], pal[3]);

        #pragma unroll
        for (int nt = 0; nt < 8; nt++) {
            int rb = (nt * 8 + g) * 68 + wn * 8 + t;
            uint32_t bh2[2] = {VHb[rb], VHb[rb + 4]};
            uint32_t bl2[2] = {VLb[rb], VLb[rb + 4]};
            mma_bf16(oacc[nt], pah, bh2);
            mma_bf16(oacc[nt], pah, bl2);
            mma_bf16(oacc[nt], pal, bh2);
        }
        __syncthreads();
        if (it < 6) issueV(it + 2);
    }

    // ---- tree-reduce 8 wn-partials (overlay on KV region) ----
    __syncthreads();
    float* red = sm + KV_W;
    auto stPart = [&](int b) {
        int base = b * 2176 + wm * 1088;
        #pragma unroll
        for (int nt = 0; nt < 8; nt++) {
            *(float2*)&red[base + g * 66 + nt * 8 + 2 * t] =
                make_float2(oacc[nt][0], oacc[nt][1]);
            *(float2*)&red[base + (g + 8) * 66 + nt * 8 + 2 * t] =
                make_float2(oacc[nt][2], oacc[nt][3]);
        }
    };
    auto addPart = [&](int b) {
        int base = b * 2176 + wm * 1088;
        #pragma unroll
        for (int nt = 0; nt < 8; nt++) {
            float2 p0 = *(float2*)&red[base + g * 66 + nt * 8 + 2 * t];
            float2 p1 = *(float2*)&red[base + (g + 8) * 66 + nt * 8 + 2 * t];
            oacc[nt][0] += p0.x; oacc[nt][1] += p0.y;
            oacc[nt][2] += p1.x; oacc[nt][3] += p1.y;
        }
    };
    if (wn >= 4) stPart(wn - 4);
    __syncthreads();
    if (wn < 4) addPart(wn);
    __syncthreads();
    if (wn == 2 || wn == 3) stPart(wn - 2);
    __syncthreads();
    if (wn < 2) addPart(wn);
    __syncthreads();
    if (wn == 1) stPart(0);
    __syncthreads();
    if (wn == 0) {
        addPart(0);
        size_t ob = (size_t)(bh >> 4) * Nn * Ee + (size_t)(bh & 15) * 64;
        #pragma unroll
        for (int nt = 0; nt < 8; nt++) {
            int col = nt * 8 + 2 * t;
            *(float2*)&out_attn[ob + (size_t)rowg * Ee + col] =
                make_float2(oacc[nt][0], oacc[nt][1]);
            *(float2*)&out_attn[ob + (size_t)(rowg + 8) * Ee + col] =
                make_float2(oacc[nt][2], oacc[nt][3]);
        }
    }
}

// ---------------------------------------------------------------------------
extern "C" void kernel_launch(void* const* d_in, const int* in_sizes, int n_in,
                              void* d_out, int out_size) {
    const float* query = (const float*)d_in[0];
    const float* key_  = (const float*)d_in[1];
    const float* value = (const float*)d_in[2];
    const float* ab    = (const float*)d_in[3];
    const float* Wq    = (const float*)d_in[4];
    const float* bq    = (const float*)d_in[5];
    const float* Wk    = (const float*)d_in[6];
    const float* bk    = (const float*)d_in[7];
    const float* Wv    = (const float*)d_in[8];
    const float* bv    = (const float*)d_in[9];

    float* out = (float*)d_out;
    const long long attn_elems = (long long)Bc * Nn * Ee;
    const long long w_elems    = (long long)BHn * Nn * Nn;
    float* attn_out = out;
    float* w_out = nullptr;
    if ((long long)out_size >= attn_elems + w_elems) w_out = out + attn_elems;

    {
        dim3 grid(4096, 6);
        pack_kernel<<<grid, 256>>>(query, key_, value, Wq, Wk, Wv);
    }
    {
        cudaFuncSetAttribute(proj_mma_kernel, cudaFuncAttributeMaxDynamicSharedMemorySize,
                             PROJ_SMEM_BYTES);
        dim3 grid(Mtot / 128, Ee / 128, 3);
        proj_mma_kernel<<<grid, 256, PROJ_SMEM_BYTES>>>(bq, bk, bv);
    }
    {
        dim3 grid(8, 64);
        vt_kernel<<<grid, 256>>>();
    }
    {
        cudaFuncSetAttribute(attn_mma_kernel, cudaFuncAttributeMaxDynamicSharedMemorySize,
                             ATTN_SMEM_BYTES);
        dim3 grid(Nn / 32, BHn);
        attn_mma_kernel<<<grid, 512, ATTN_SMEM_BYTES>>>(ab, attn_out, w_out);
    }
}